// round 5
// baseline (speedup 1.0000x reference)
#include <cuda_runtime.h>
#include <cuda_bf16.h>

// ---------------------------------------------------------------------------
// CNN_ODE: conv1d+SiLU -> MLP encoder -> 50-step fixed dopri5 (64-dim neural
// ODE) -> regressor.  B = 65536 independent samples.
//
// Inputs (metadata order):
//  0 x[B,40,24]  1 t_span[2]  2 conv_w[36,24,3]  3 conv_b[36]
//  4 enc1_w[128,1440]  5 enc1_b[128]  6 enc2_w[64,128]  7 enc2_b[64]
//  8 ode1_w[64,64]  9 ode1_b[64]  10 ode2_w[64,64]  11 ode2_b[64]
// 12 reg1_w[32,64] 13 reg1_b[32] 14 reg2_w[1,32] 15 reg2_b[1]
// Output: pred[B] float32.
// ---------------------------------------------------------------------------

#define SEQ   40
#define INC   24
#define NK    36
#define FLAT  1440
#define HID   64
#define STEPS 50

__device__ float g_theta0[65536 * HID];   // encoder output / ODE initial state

// ============================== Encoder ====================================
// 8 samples per CTA, 256 threads.
#define ENC_SPB    8
#define SC_STRIDE  1444                    // 1444 % 32 == 4 -> conflict-free f4
#define SW_STRIDE  33                      // scalar conflict-free
#define ENC_SMEM_FLOATS (ENC_SPB*SC_STRIDE + ENC_SPB*128 + 128*SW_STRIDE)

__global__ void __launch_bounds__(256) enc_kernel(
    const float* __restrict__ x,
    const float* __restrict__ conv_w, const float* __restrict__ conv_b,
    const float* __restrict__ enc1_w, const float* __restrict__ enc1_b,
    const float* __restrict__ enc2_w, const float* __restrict__ enc2_b)
{
    extern __shared__ float sm[];
    float* sC  = sm;                                // [8][SC_STRIDE]
    float* sH1 = sC  + ENC_SPB * SC_STRIDE;         // [8][128]
    float* sW  = sH1 + ENC_SPB * 128;               // [128][33] weight chunk

    const int tid = threadIdx.x;
    const long long blk = blockIdx.x;

    // ---- conv1d (pad=1) + SiLU -> sC (flatten order k*SEQ + s) ----
    for (int t = tid; t < NK * ENC_SPB; t += 256) {
        const int k  = t % NK;
        const int sp = t / NK;
        const float* xs = x + (blk * ENC_SPB + sp) * (SEQ * INC);
        float o[SEQ];
        const float bk = __ldg(&conv_b[k]);
#pragma unroll
        for (int s = 0; s < SEQ; s++) o[s] = bk;
        for (int c = 0; c < INC; c++) {
            const float w0 = __ldg(&conv_w[k * 72 + c * 3 + 0]);
            const float w1 = __ldg(&conv_w[k * 72 + c * 3 + 1]);
            const float w2 = __ldg(&conv_w[k * 72 + c * 3 + 2]);
            float prev = 0.0f;
            float cur  = __ldg(&xs[0 * INC + c]);
#pragma unroll
            for (int s = 0; s < SEQ; s++) {
                const float nxt = (s + 1 < SEQ) ? __ldg(&xs[(s + 1) * INC + c]) : 0.0f;
                o[s] = fmaf(w0, prev, o[s]);
                o[s] = fmaf(w1, cur,  o[s]);
                o[s] = fmaf(w2, nxt,  o[s]);
                prev = cur; cur = nxt;
            }
        }
#pragma unroll
        for (int s = 0; s < SEQ; s++) {
            const float v  = o[s];
            const float sg = __fdividef(1.0f, 1.0f + __expf(-v));   // sigmoid
            sC[sp * SC_STRIDE + k * SEQ + s] = v * sg;              // SiLU
        }
    }
    __syncthreads();

    // ---- enc1: [1440 -> 128] + ReLU, shared-staged weight chunks ----
    {
        const int oc   = tid & 127;
        const int half = tid >> 7;                  // 0 -> samples 0..3, 1 -> 4..7
        float a0 = __ldg(&enc1_b[oc]);
        float a1 = a0, a2 = a0, a3 = a0;
        const float* c0 = sC + (half * 4 + 0) * SC_STRIDE;
        const float* c1 = sC + (half * 4 + 1) * SC_STRIDE;
        const float* c2 = sC + (half * 4 + 2) * SC_STRIDE;
        const float* c3 = sC + (half * 4 + 3) * SC_STRIDE;

        for (int i0 = 0; i0 < FLAT; i0 += 32) {
            __syncthreads();                         // chunk reuse guard
            for (int l = tid; l < 128 * 32; l += 256) {
                const int r  = l >> 5;
                const int ii = l & 31;
                sW[r * SW_STRIDE + ii] = __ldg(&enc1_w[(size_t)r * FLAT + i0 + ii]);
            }
            __syncthreads();
#pragma unroll
            for (int ii = 0; ii < 32; ii++) {
                const float w = sW[oc * SW_STRIDE + ii];
                a0 = fmaf(w, c0[i0 + ii], a0);
                a1 = fmaf(w, c1[i0 + ii], a1);
                a2 = fmaf(w, c2[i0 + ii], a2);
                a3 = fmaf(w, c3[i0 + ii], a3);
            }
        }
        sH1[(half * 4 + 0) * 128 + oc] = fmaxf(a0, 0.0f);
        sH1[(half * 4 + 1) * 128 + oc] = fmaxf(a1, 0.0f);
        sH1[(half * 4 + 2) * 128 + oc] = fmaxf(a2, 0.0f);
        sH1[(half * 4 + 3) * 128 + oc] = fmaxf(a3, 0.0f);
    }
    __syncthreads();

    // ---- enc2: [128 -> 64] (linear) -> g_theta0 ----
    for (int t = tid; t < ENC_SPB * HID; t += 256) {
        const int sp = t >> 6;
        const int oc = t & 63;
        float acc = __ldg(&enc2_b[oc]);
        const float* wr = enc2_w + oc * 128;
        const float* hv = sH1 + sp * 128;
        for (int i = 0; i < 128; i += 4) {
            const float4 wv = __ldg((const float4*)(wr + i));
            const float4 h4 = *(const float4*)(hv + i);
            acc = fmaf(wv.x, h4.x, fmaf(wv.y, h4.y, fmaf(wv.z, h4.z, fmaf(wv.w, h4.w, acc))));
        }
        g_theta0[(blk * ENC_SPB + sp) * HID + oc] = acc;
    }
}

// ================================ ODE ======================================
// 32 samples per CTA, 256 threads: tid = sp*8 + q; thread owns dims j*8+q.
#define ODE_SPB 32
#define WS 68                                      // 68 % 32 == 4
#define ODE_SMEM_FLOATS (2*HID*WS + 2*HID + 2*ODE_SPB*WS)

__device__ __forceinline__ void eval_f(
    const float* __restrict__ sW1, const float* __restrict__ sW2,
    const float* __restrict__ sb1, const float* __restrict__ sb2,
    const float* __restrict__ sA,  float* __restrict__ sB,
    const int sp, const int q, float (&k)[8])
{
    float acc[8];
#pragma unroll
    for (int j = 0; j < 8; j++) acc[j] = sb1[j * 8 + q];
#pragma unroll
    for (int i = 0; i < HID; i += 4) {
        const float4 yv = *(const float4*)(sA + sp * WS + i);
#pragma unroll
        for (int j = 0; j < 8; j++) {
            const float4 wv = *(const float4*)(sW1 + (j * 8 + q) * WS + i);
            acc[j] = fmaf(wv.x, yv.x, fmaf(wv.y, yv.y, fmaf(wv.z, yv.z, fmaf(wv.w, yv.w, acc[j]))));
        }
    }
#pragma unroll
    for (int j = 0; j < 8; j++) {
        const float e = __expf(2.0f * acc[j]);
        sB[sp * WS + j * 8 + q] = 1.0f - __fdividef(2.0f, e + 1.0f);  // tanh
    }
    __syncthreads();
#pragma unroll
    for (int j = 0; j < 8; j++) acc[j] = sb2[j * 8 + q];
#pragma unroll
    for (int i = 0; i < HID; i += 4) {
        const float4 hv = *(const float4*)(sB + sp * WS + i);
#pragma unroll
        for (int j = 0; j < 8; j++) {
            const float4 wv = *(const float4*)(sW2 + (j * 8 + q) * WS + i);
            acc[j] = fmaf(wv.x, hv.x, fmaf(wv.y, hv.y, fmaf(wv.z, hv.z, fmaf(wv.w, hv.w, acc[j]))));
        }
    }
#pragma unroll
    for (int j = 0; j < 8; j++) k[j] = acc[j];
}

__global__ void __launch_bounds__(256, 2) ode_kernel(
    const float* __restrict__ t_span,
    const float* __restrict__ w1g, const float* __restrict__ b1g,
    const float* __restrict__ w2g, const float* __restrict__ b2g,
    const float* __restrict__ r1w, const float* __restrict__ r1b,
    const float* __restrict__ r2w, const float* __restrict__ r2b,
    float* __restrict__ out)
{
    extern __shared__ float sm[];
    float* sW1 = sm;                      // [64][WS]
    float* sW2 = sW1 + HID * WS;          // [64][WS]
    float* sb1 = sW2 + HID * WS;          // [64]
    float* sb2 = sb1 + HID;               // [64]
    float* sA  = sb2 + HID;               // [32][WS] stage input
    float* sB  = sA  + ODE_SPB * WS;      // [32][WS] hidden

    const int tid = threadIdx.x;
    const int sp  = tid >> 3;             // 0..31
    const int q   = tid & 7;              // 0..7

    for (int i = tid; i < HID * HID; i += 256) {
        const int r = i >> 6, c = i & 63;
        sW1[r * WS + c] = w1g[i];
        sW2[r * WS + c] = w2g[i];
    }
    if (tid < HID) { sb1[tid] = b1g[tid]; sb2[tid] = b2g[tid]; }

    const float dt = (__ldg(&t_span[1]) - __ldg(&t_span[0])) * (1.0f / STEPS);

    const long long gsp = (long long)blockIdx.x * ODE_SPB + sp;
    float y[8];
#pragma unroll
    for (int j = 0; j < 8; j++) {
        y[j] = g_theta0[gsp * HID + j * 8 + q];
        sA[sp * WS + j * 8 + q] = y[j];
    }

    float k1[8], k2[8], k3[8], k4[8], k5[8], k6[8];

    for (int step = 0; step < STEPS; step++) {
        __syncthreads();
        eval_f(sW1, sW2, sb1, sb2, sA, sB, sp, q, k1);
        {
            const float c1 = dt * (1.0f / 5.0f);
#pragma unroll
            for (int j = 0; j < 8; j++) sA[sp * WS + j * 8 + q] = fmaf(c1, k1[j], y[j]);
        }
        __syncthreads();
        eval_f(sW1, sW2, sb1, sb2, sA, sB, sp, q, k2);
        {
            const float c1 = dt * (3.0f / 40.0f), c2 = dt * (9.0f / 40.0f);
#pragma unroll
            for (int j = 0; j < 8; j++)
                sA[sp * WS + j * 8 + q] = fmaf(c1, k1[j], fmaf(c2, k2[j], y[j]));
        }
        __syncthreads();
        eval_f(sW1, sW2, sb1, sb2, sA, sB, sp, q, k3);
        {
            const float c1 = dt * (44.0f / 45.0f), c2 = dt * (-56.0f / 15.0f),
                        c3 = dt * (32.0f / 9.0f);
#pragma unroll
            for (int j = 0; j < 8; j++)
                sA[sp * WS + j * 8 + q] =
                    fmaf(c1, k1[j], fmaf(c2, k2[j], fmaf(c3, k3[j], y[j])));
        }
        __syncthreads();
        eval_f(sW1, sW2, sb1, sb2, sA, sB, sp, q, k4);
        {
            const float c1 = dt * (19372.0f / 6561.0f), c2 = dt * (-25360.0f / 2187.0f),
                        c3 = dt * (64448.0f / 6561.0f), c4 = dt * (-212.0f / 729.0f);
#pragma unroll
            for (int j = 0; j < 8; j++)
                sA[sp * WS + j * 8 + q] =
                    fmaf(c1, k1[j], fmaf(c2, k2[j], fmaf(c3, k3[j], fmaf(c4, k4[j], y[j]))));
        }
        __syncthreads();
        eval_f(sW1, sW2, sb1, sb2, sA, sB, sp, q, k5);
        {
            const float c1 = dt * (9017.0f / 3168.0f), c2 = dt * (-355.0f / 33.0f),
                        c3 = dt * (46732.0f / 5247.0f), c4 = dt * (49.0f / 176.0f),
                        c5 = dt * (-5103.0f / 18656.0f);
#pragma unroll
            for (int j = 0; j < 8; j++)
                sA[sp * WS + j * 8 + q] =
                    fmaf(c1, k1[j], fmaf(c2, k2[j], fmaf(c3, k3[j],
                    fmaf(c4, k4[j], fmaf(c5, k5[j], y[j])))));
        }
        __syncthreads();
        eval_f(sW1, sW2, sb1, sb2, sA, sB, sp, q, k6);
        {
            const float b1 = dt * (35.0f / 384.0f), b3 = dt * (500.0f / 1113.0f),
                        b4 = dt * (125.0f / 192.0f), b5 = dt * (-2187.0f / 6784.0f),
                        b6 = dt * (11.0f / 84.0f);
#pragma unroll
            for (int j = 0; j < 8; j++) {
                y[j] = fmaf(b1, k1[j], fmaf(b3, k3[j], fmaf(b4, k4[j],
                       fmaf(b5, k5[j], fmaf(b6, k6[j], y[j])))));
                sA[sp * WS + j * 8 + q] = y[j];
            }
        }
    }
    __syncthreads();

    // ---- regressor: pred = reg2_b + sum_m reg2_w[m]*relu(reg1_w[m]·y + reg1_b[m])
    float part = 0.0f;
#pragma unroll
    for (int mm = 0; mm < 4; mm++) {
        const int m = mm * 8 + q;
        float acc = __ldg(&r1b[m]);
        const float* wr = r1w + m * HID;
#pragma unroll
        for (int i = 0; i < HID; i += 4) {
            const float4 wv = __ldg((const float4*)(wr + i));
            const float4 yv = *(const float4*)(sA + sp * WS + i);
            acc = fmaf(wv.x, yv.x, fmaf(wv.y, yv.y, fmaf(wv.z, yv.z, fmaf(wv.w, yv.w, acc))));
        }
        part = fmaf(__ldg(&r2w[m]), fmaxf(acc, 0.0f), part);
    }
    part += __shfl_down_sync(0xffffffffu, part, 4);
    part += __shfl_down_sync(0xffffffffu, part, 2);
    part += __shfl_down_sync(0xffffffffu, part, 1);
    if (q == 0) out[gsp] = part + __ldg(&r2b[0]);
}

// ============================== launch ======================================
extern "C" void kernel_launch(void* const* d_in, const int* in_sizes, int n_in,
                              void* d_out, int out_size)
{
    const float* x      = (const float*)d_in[0];
    const float* t_span = (const float*)d_in[1];
    const float* conv_w = (const float*)d_in[2];
    const float* conv_b = (const float*)d_in[3];
    const float* enc1_w = (const float*)d_in[4];
    const float* enc1_b = (const float*)d_in[5];
    const float* enc2_w = (const float*)d_in[6];
    const float* enc2_b = (const float*)d_in[7];
    const float* ode1_w = (const float*)d_in[8];
    const float* ode1_b = (const float*)d_in[9];
    const float* ode2_w = (const float*)d_in[10];
    const float* ode2_b = (const float*)d_in[11];
    const float* reg1_w = (const float*)d_in[12];
    const float* reg1_b = (const float*)d_in[13];
    const float* reg2_w = (const float*)d_in[14];
    const float* reg2_b = (const float*)d_in[15];
    float* out = (float*)d_out;

    const int B = in_sizes[0] / (SEQ * INC);

    const int enc_smem = ENC_SMEM_FLOATS * (int)sizeof(float);
    const int ode_smem = ODE_SMEM_FLOATS * (int)sizeof(float);
    cudaFuncSetAttribute(enc_kernel, cudaFuncAttributeMaxDynamicSharedMemorySize, enc_smem);
    cudaFuncSetAttribute(ode_kernel, cudaFuncAttributeMaxDynamicSharedMemorySize, ode_smem);

    enc_kernel<<<B / ENC_SPB, 256, enc_smem>>>(
        x, conv_w, conv_b, enc1_w, enc1_b, enc2_w, enc2_b);
    ode_kernel<<<B / ODE_SPB, 256, ode_smem>>>(
        t_span, ode1_w, ode1_b, ode2_w, ode2_b,
        reg1_w, reg1_b, reg2_w, reg2_b, out);
}

// round 6
// speedup vs baseline: 1.9174x; 1.9174x over previous
#include <cuda_runtime.h>
#include <cuda_bf16.h>

// ---------------------------------------------------------------------------
// CNN_ODE: conv1d+SiLU -> MLP encoder -> 50-step fixed dopri5 (64-dim neural
// ODE) -> regressor.  B = 65536 independent samples.
// ---------------------------------------------------------------------------

#define SEQ   40
#define INC   24
#define NK    36
#define FLAT  1440
#define HID   64
#define STEPS 50

typedef unsigned long long ull;

// theta0 scratch, TRANSPOSED: float layout [dim][sample]  (= ull [dim][pair])
__device__ ull g_theta0[HID * 32768];   // 64 * 32768 pairs = 16 MB

// ========================== f32x2 helpers ==================================
__device__ __forceinline__ ull dup2(float x) {
    ull r; asm("mov.b64 %0,{%1,%1};" : "=l"(r) : "f"(x)); return r;
}
__device__ __forceinline__ ull pk2(float a, float b) {
    ull r; asm("mov.b64 %0,{%1,%2};" : "=l"(r) : "f"(a), "f"(b)); return r;
}
__device__ __forceinline__ float2 un2(ull v) {
    float2 f; asm("mov.b64 {%0,%1},%2;" : "=f"(f.x), "=f"(f.y) : "l"(v)); return f;
}
__device__ __forceinline__ ull fma2(ull a, ull b, ull c) {
    ull d; asm("fma.rn.f32x2 %0,%1,%2,%3;" : "=l"(d) : "l"(a), "l"(b), "l"(c));
    return d;
}

// ============================== Encoder ====================================
#define ENC_SPB    8
#define SC_STRIDE  1444                    // %32==4, %4==0 (float4 + banks ok)
#define SW_STRIDE  36                      // float4-aligned, %32==4
#define ENC_SMEM_FLOATS (ENC_SPB*SC_STRIDE + ENC_SPB*128 + 128*SW_STRIDE)

__global__ void __launch_bounds__(256) enc_kernel(
    const float* __restrict__ x,
    const float* __restrict__ conv_w, const float* __restrict__ conv_b,
    const float* __restrict__ enc1_w, const float* __restrict__ enc1_b,
    const float* __restrict__ enc2_w, const float* __restrict__ enc2_b,
    int B)
{
    extern __shared__ float sm[];
    float* sC  = sm;                                // [8][SC_STRIDE]
    float* sH1 = sC  + ENC_SPB * SC_STRIDE;         // [8][128]
    float* sW  = sH1 + ENC_SPB * 128;               // [128][36]

    const int tid = threadIdx.x;
    const long long blk = blockIdx.x;

    // ---- conv1d (pad=1) + SiLU -> sC (flatten order k*SEQ + s) ----
    for (int t = tid; t < NK * ENC_SPB; t += 256) {
        const int k  = t % NK;
        const int sp = t / NK;
        const float* xs = x + (blk * ENC_SPB + sp) * (SEQ * INC);
        float o[SEQ];
        const float bk = __ldg(&conv_b[k]);
#pragma unroll
        for (int s = 0; s < SEQ; s++) o[s] = bk;
        for (int c = 0; c < INC; c++) {
            const float w0 = __ldg(&conv_w[k * 72 + c * 3 + 0]);
            const float w1 = __ldg(&conv_w[k * 72 + c * 3 + 1]);
            const float w2 = __ldg(&conv_w[k * 72 + c * 3 + 2]);
            float prev = 0.0f;
            float cur  = __ldg(&xs[0 * INC + c]);
#pragma unroll
            for (int s = 0; s < SEQ; s++) {
                const float nxt = (s + 1 < SEQ) ? __ldg(&xs[(s + 1) * INC + c]) : 0.0f;
                o[s] = fmaf(w0, prev, o[s]);
                o[s] = fmaf(w1, cur,  o[s]);
                o[s] = fmaf(w2, nxt,  o[s]);
                prev = cur; cur = nxt;
            }
        }
#pragma unroll
        for (int s = 0; s < SEQ; s++) {
            const float v  = o[s];
            const float sg = __fdividef(1.0f, 1.0f + __expf(-v));
            sC[sp * SC_STRIDE + k * SEQ + s] = v * sg;
        }
    }
    __syncthreads();

    // ---- enc1: [1440 -> 128] + ReLU (float4 inner) ----
    {
        const int oc   = tid & 127;
        const int half = tid >> 7;
        float a0 = __ldg(&enc1_b[oc]);
        float a1 = a0, a2 = a0, a3 = a0;
        const float* c0 = sC + (half * 4 + 0) * SC_STRIDE;
        const float* c1 = sC + (half * 4 + 1) * SC_STRIDE;
        const float* c2 = sC + (half * 4 + 2) * SC_STRIDE;
        const float* c3 = sC + (half * 4 + 3) * SC_STRIDE;

        for (int i0 = 0; i0 < FLAT; i0 += 32) {
            __syncthreads();
            for (int l = tid; l < 128 * 32; l += 256) {
                const int r  = l >> 5;
                const int ii = l & 31;
                sW[r * SW_STRIDE + ii] = __ldg(&enc1_w[(size_t)r * FLAT + i0 + ii]);
            }
            __syncthreads();
#pragma unroll
            for (int ii = 0; ii < 32; ii += 4) {
                const float4 w  = *(const float4*)(sW + oc * SW_STRIDE + ii);
                const float4 v0 = *(const float4*)(c0 + i0 + ii);
                const float4 v1 = *(const float4*)(c1 + i0 + ii);
                const float4 v2 = *(const float4*)(c2 + i0 + ii);
                const float4 v3 = *(const float4*)(c3 + i0 + ii);
                a0 = fmaf(w.x,v0.x, fmaf(w.y,v0.y, fmaf(w.z,v0.z, fmaf(w.w,v0.w, a0))));
                a1 = fmaf(w.x,v1.x, fmaf(w.y,v1.y, fmaf(w.z,v1.z, fmaf(w.w,v1.w, a1))));
                a2 = fmaf(w.x,v2.x, fmaf(w.y,v2.y, fmaf(w.z,v2.z, fmaf(w.w,v2.w, a2))));
                a3 = fmaf(w.x,v3.x, fmaf(w.y,v3.y, fmaf(w.z,v3.z, fmaf(w.w,v3.w, a3))));
            }
        }
        sH1[(half * 4 + 0) * 128 + oc] = fmaxf(a0, 0.0f);
        sH1[(half * 4 + 1) * 128 + oc] = fmaxf(a1, 0.0f);
        sH1[(half * 4 + 2) * 128 + oc] = fmaxf(a2, 0.0f);
        sH1[(half * 4 + 3) * 128 + oc] = fmaxf(a3, 0.0f);
    }
    __syncthreads();

    // ---- enc2: [128 -> 64] -> g_theta0 TRANSPOSED [dim][sample] ----
    float* gT = (float*)g_theta0;
    for (int t = tid; t < ENC_SPB * HID; t += 256) {
        const int sp = t >> 6;
        const int oc = t & 63;
        float acc = __ldg(&enc2_b[oc]);
        const float* wr = enc2_w + oc * 128;
        const float* hv = sH1 + sp * 128;
#pragma unroll
        for (int i = 0; i < 128; i += 4) {
            const float4 wv = __ldg((const float4*)(wr + i));
            const float4 h4 = *(const float4*)(hv + i);
            acc = fmaf(wv.x, h4.x, fmaf(wv.y, h4.y, fmaf(wv.z, h4.z, fmaf(wv.w, h4.w, acc))));
        }
        gT[(size_t)oc * B + (blk * ENC_SPB + sp)] = acc;
    }
}

// ================================ ODE ======================================
// 64 samples per CTA (32 f32x2 pairs). warp q owns dims [8q, 8q+8);
// lane l owns sample pair l. Weights: all-lane broadcast LDS. Activations:
// lane-coalesced ull LDS at [i*32 + l].
#define ODE_SPB 64
#define ODE_SMEM_BYTES (3*2048*8 + 2*4096*4 + 128*4)   // sY,sA,sB + W1,W2 + b

__device__ __forceinline__ void matvec8(
    const float* __restrict__ sW, const float* __restrict__ sb,
    const ull* __restrict__ sIn, const int dbase, const int l, ull (&acc)[8])
{
#pragma unroll
    for (int j = 0; j < 8; j++) acc[j] = dup2(sb[dbase + j]);
#pragma unroll
    for (int i = 0; i < HID; i += 4) {
        const ull y0 = sIn[(i + 0) * 32 + l];
        const ull y1 = sIn[(i + 1) * 32 + l];
        const ull y2 = sIn[(i + 2) * 32 + l];
        const ull y3 = sIn[(i + 3) * 32 + l];
#pragma unroll
        for (int j = 0; j < 8; j++) {
            const float4 w = *(const float4*)(sW + (dbase + j) * HID + i);
            acc[j] = fma2(dup2(w.x), y0, acc[j]);
            acc[j] = fma2(dup2(w.y), y1, acc[j]);
            acc[j] = fma2(dup2(w.z), y2, acc[j]);
            acc[j] = fma2(dup2(w.w), y3, acc[j]);
        }
    }
}

__device__ __forceinline__ void eval2(
    const float* __restrict__ sW1, const float* __restrict__ sW2,
    const float* __restrict__ sb1, const float* __restrict__ sb2,
    const ull* __restrict__ sA, ull* __restrict__ sB,
    const int dbase, const int l, ull (&k)[8])
{
    ull acc[8];
    matvec8(sW1, sb1, sA, dbase, l, acc);
#pragma unroll
    for (int j = 0; j < 8; j++) {
        float2 v = un2(acc[j]);
        v.x = 1.0f - __fdividef(2.0f, __expf(2.0f * v.x) + 1.0f);   // tanh
        v.y = 1.0f - __fdividef(2.0f, __expf(2.0f * v.y) + 1.0f);
        sB[(dbase + j) * 32 + l] = pk2(v.x, v.y);
    }
    __syncthreads();
    matvec8(sW2, sb2, sB, dbase, l, k);
}

__global__ void __launch_bounds__(256, 2) ode_kernel(
    const float* __restrict__ t_span,
    const float* __restrict__ w1g, const float* __restrict__ b1g,
    const float* __restrict__ w2g, const float* __restrict__ b2g,
    const float* __restrict__ r1w, const float* __restrict__ r1b,
    const float* __restrict__ r2w, const float* __restrict__ r2b,
    float* __restrict__ out, int B)
{
    extern __shared__ char smraw[];
    ull*   sY  = (ull*)smraw;          // [64 dims][32 pairs]
    ull*   sA  = sY + 2048;
    ull*   sB  = sA + 2048;
    float* sW1 = (float*)(sB + 2048);  // [64][64]
    float* sW2 = sW1 + 4096;
    float* sb1 = sW2 + 4096;
    float* sb2 = sb1 + 64;

    const int tid   = threadIdx.x;
    const int q     = tid >> 5;        // warp -> dim group
    const int l     = tid & 31;        // lane -> sample pair
    const int dbase = q * 8;

    for (int i = tid; i < HID * HID; i += 256) { sW1[i] = w1g[i]; sW2[i] = w2g[i]; }
    if (tid < HID) { sb1[tid] = b1g[tid]; sb2[tid] = b2g[tid]; }

    const float dt = (__ldg(&t_span[1]) - __ldg(&t_span[0])) * (1.0f / STEPS);

    // init: coalesced ull loads from transposed theta0
    const int PS = B >> 1;                         // pairs stride
    const int pairBase = blockIdx.x * 32;
    for (int t = tid; t < 2048; t += 256) {
        const int d = t >> 5, p = t & 31;
        const ull v = g_theta0[(size_t)d * PS + pairBase + p];
        sY[t] = v; sA[t] = v;
    }

    ull k1[8], k2[8], k3[8], k4[8], k5[8];

    for (int step = 0; step < STEPS; step++) {
        __syncthreads();
        eval2(sW1, sW2, sb1, sb2, sA, sB, dbase, l, k1);
        {
            const ull c1 = dup2(dt * 0.2f);
#pragma unroll
            for (int j = 0; j < 8; j++)
                sA[(dbase + j) * 32 + l] = fma2(c1, k1[j], sY[(dbase + j) * 32 + l]);
        }
        __syncthreads();
        eval2(sW1, sW2, sb1, sb2, sA, sB, dbase, l, k2);
        {
            const ull c1 = dup2(dt * (3.0f / 40.0f)), c2 = dup2(dt * (9.0f / 40.0f));
#pragma unroll
            for (int j = 0; j < 8; j++)
                sA[(dbase + j) * 32 + l] =
                    fma2(c1, k1[j], fma2(c2, k2[j], sY[(dbase + j) * 32 + l]));
        }
        __syncthreads();
        eval2(sW1, sW2, sb1, sb2, sA, sB, dbase, l, k3);
        {
            const ull c1 = dup2(dt * (44.0f / 45.0f)), c2 = dup2(dt * (-56.0f / 15.0f)),
                      c3 = dup2(dt * (32.0f / 9.0f));
#pragma unroll
            for (int j = 0; j < 8; j++)
                sA[(dbase + j) * 32 + l] =
                    fma2(c1, k1[j], fma2(c2, k2[j], fma2(c3, k3[j],
                    sY[(dbase + j) * 32 + l])));
        }
        __syncthreads();
        eval2(sW1, sW2, sb1, sb2, sA, sB, dbase, l, k4);
        {
            const ull c1 = dup2(dt * (19372.0f / 6561.0f)), c2 = dup2(dt * (-25360.0f / 2187.0f)),
                      c3 = dup2(dt * (64448.0f / 6561.0f)), c4 = dup2(dt * (-212.0f / 729.0f));
#pragma unroll
            for (int j = 0; j < 8; j++)
                sA[(dbase + j) * 32 + l] =
                    fma2(c1, k1[j], fma2(c2, k2[j], fma2(c3, k3[j], fma2(c4, k4[j],
                    sY[(dbase + j) * 32 + l]))));
        }
        __syncthreads();
        eval2(sW1, sW2, sb1, sb2, sA, sB, dbase, l, k5);
        {
            const ull c1 = dup2(dt * (9017.0f / 3168.0f)), c2 = dup2(dt * (-355.0f / 33.0f)),
                      c3 = dup2(dt * (46732.0f / 5247.0f)), c4 = dup2(dt * (49.0f / 176.0f)),
                      c5 = dup2(dt * (-5103.0f / 18656.0f));
#pragma unroll
            for (int j = 0; j < 8; j++)
                sA[(dbase + j) * 32 + l] =
                    fma2(c1, k1[j], fma2(c2, k2[j], fma2(c3, k3[j], fma2(c4, k4[j],
                    fma2(c5, k5[j], sY[(dbase + j) * 32 + l])))));
        }
        __syncthreads();
        {
            ull k6[8];
            eval2(sW1, sW2, sb1, sb2, sA, sB, dbase, l, k6);
            const ull b1 = dup2(dt * (35.0f / 384.0f)),  b3 = dup2(dt * (500.0f / 1113.0f)),
                      b4 = dup2(dt * (125.0f / 192.0f)), b5 = dup2(dt * (-2187.0f / 6784.0f)),
                      b6 = dup2(dt * (11.0f / 84.0f));
#pragma unroll
            for (int j = 0; j < 8; j++) {
                const ull yn =
                    fma2(b1, k1[j], fma2(b3, k3[j], fma2(b4, k4[j],
                    fma2(b5, k5[j], fma2(b6, k6[j], sY[(dbase + j) * 32 + l])))));
                sY[(dbase + j) * 32 + l] = yn;
                sA[(dbase + j) * 32 + l] = yn;
            }
        }
    }
    __syncthreads();

    // ---- regressor: 4 threads per sample, 8 reg1 rows each ----
    {
        const int s  = tid >> 2;          // local sample 0..63
        const int mg = (tid & 3) * 8;
        const int pr = s >> 1, hb = s & 1;
        float accm[8];
#pragma unroll
        for (int m = 0; m < 8; m++) accm[m] = __ldg(&r1b[mg + m]);
        for (int i = 0; i < HID; i++) {
            const float2 yv = un2(sY[i * 32 + pr]);
            const float  yy = hb ? yv.y : yv.x;
#pragma unroll
            for (int m = 0; m < 8; m++)
                accm[m] = fmaf(__ldg(&r1w[(mg + m) * HID + i]), yy, accm[m]);
        }
        float part = 0.0f;
#pragma unroll
        for (int m = 0; m < 8; m++)
            part = fmaf(__ldg(&r2w[mg + m]), fmaxf(accm[m], 0.0f), part);
        part += __shfl_xor_sync(0xffffffffu, part, 1);
        part += __shfl_xor_sync(0xffffffffu, part, 2);
        if ((tid & 3) == 0)
            out[(long long)blockIdx.x * ODE_SPB + s] = part + __ldg(&r2b[0]);
    }
}

// ============================== launch ======================================
extern "C" void kernel_launch(void* const* d_in, const int* in_sizes, int n_in,
                              void* d_out, int out_size)
{
    const float* x      = (const float*)d_in[0];
    const float* t_span = (const float*)d_in[1];
    const float* conv_w = (const float*)d_in[2];
    const float* conv_b = (const float*)d_in[3];
    const float* enc1_w = (const float*)d_in[4];
    const float* enc1_b = (const float*)d_in[5];
    const float* enc2_w = (const float*)d_in[6];
    const float* enc2_b = (const float*)d_in[7];
    const float* ode1_w = (const float*)d_in[8];
    const float* ode1_b = (const float*)d_in[9];
    const float* ode2_w = (const float*)d_in[10];
    const float* ode2_b = (const float*)d_in[11];
    const float* reg1_w = (const float*)d_in[12];
    const float* reg1_b = (const float*)d_in[13];
    const float* reg2_w = (const float*)d_in[14];
    const float* reg2_b = (const float*)d_in[15];
    float* out = (float*)d_out;

    const int B = in_sizes[0] / (SEQ * INC);

    const int enc_smem = ENC_SMEM_FLOATS * (int)sizeof(float);
    const int ode_smem = ODE_SMEM_BYTES;
    cudaFuncSetAttribute(enc_kernel, cudaFuncAttributeMaxDynamicSharedMemorySize, enc_smem);
    cudaFuncSetAttribute(ode_kernel, cudaFuncAttributeMaxDynamicSharedMemorySize, ode_smem);

    enc_kernel<<<B / ENC_SPB, 256, enc_smem>>>(
        x, conv_w, conv_b, enc1_w, enc1_b, enc2_w, enc2_b, B);
    ode_kernel<<<B / ODE_SPB, 256, ode_smem>>>(
        t_span, ode1_w, ode1_b, ode2_w, ode2_b,
        reg1_w, reg1_b, reg2_w, reg2_b, out, B);
}

// round 7
// speedup vs baseline: 2.1261x; 1.1089x over previous
#include <cuda_runtime.h>
#include <cuda_bf16.h>

// ---------------------------------------------------------------------------
// CNN_ODE: conv1d+SiLU -> MLP encoder -> 50-step fixed dopri5 (64-dim neural
// ODE) -> regressor.  B = 65536 independent samples.
// ---------------------------------------------------------------------------

#define SEQ   40
#define INC   24
#define NK    36
#define FLAT  1440
#define HID   64
#define STEPS 50

typedef unsigned long long ull;

// theta0 scratch, TRANSPOSED: float layout [dim][sample] (= ull [dim][pair])
__device__ ull g_theta0[HID * 32768];   // 16 MB

// ========================== f32x2 helpers ==================================
__device__ __forceinline__ ull dup2(float x) {
    ull r; asm("mov.b64 %0,{%1,%1};" : "=l"(r) : "f"(x)); return r;
}
__device__ __forceinline__ float2 un2(ull v) {
    float2 f; asm("mov.b64 {%0,%1},%2;" : "=f"(f.x), "=f"(f.y) : "l"(v)); return f;
}
__device__ __forceinline__ ull fma2(ull a, ull b, ull c) {
    ull d; asm("fma.rn.f32x2 %0,%1,%2,%3;" : "=l"(d) : "l"(a), "l"(b), "l"(c));
    return d;
}
__device__ __forceinline__ float tanhap(float x) {
    float r; asm("tanh.approx.f32 %0,%1;" : "=f"(r) : "f"(x)); return r;
}
__device__ __forceinline__ ull tanh2(ull v) {
    float2 f = un2(v);
    ull r; asm("mov.b64 %0,{%1,%2};" : "=l"(r) : "f"(tanhap(f.x)), "f"(tanhap(f.y)));
    return r;
}

// ============================== Encoder ====================================
#define ENC_SPB    16
#define SC_STRIDE  1444                    // %32==4, %4==0
#define SW_STRIDE  36                      // float4-aligned, %32==4
#define ENC_SMEM_FLOATS (ENC_SPB*SC_STRIDE + ENC_SPB*128 + 128*SW_STRIDE)

__global__ void __launch_bounds__(256) enc_kernel(
    const float* __restrict__ x,
    const float* __restrict__ conv_w, const float* __restrict__ conv_b,
    const float* __restrict__ enc1_w, const float* __restrict__ enc1_b,
    const float* __restrict__ enc2_w, const float* __restrict__ enc2_b,
    int B)
{
    extern __shared__ float sm[];
    float* sC  = sm;                                // [16][SC_STRIDE]
    float* sH1 = sC  + ENC_SPB * SC_STRIDE;         // [16][128]
    float* sW  = sH1 + ENC_SPB * 128;               // [128][36]

    const int tid = threadIdx.x;
    const long long blk = blockIdx.x;

    // ---- conv1d (pad=1) + SiLU -> sC (flatten order k*SEQ + s) ----
    for (int t = tid; t < NK * ENC_SPB; t += 256) {
        const int k  = t % NK;
        const int sp = t / NK;
        const float* xs = x + (blk * ENC_SPB + sp) * (SEQ * INC);
        float o[SEQ];
        const float bk = __ldg(&conv_b[k]);
#pragma unroll
        for (int s = 0; s < SEQ; s++) o[s] = bk;
        for (int c = 0; c < INC; c++) {
            const float w0 = __ldg(&conv_w[k * 72 + c * 3 + 0]);
            const float w1 = __ldg(&conv_w[k * 72 + c * 3 + 1]);
            const float w2 = __ldg(&conv_w[k * 72 + c * 3 + 2]);
            float prev = 0.0f;
            float cur  = __ldg(&xs[0 * INC + c]);
#pragma unroll
            for (int s = 0; s < SEQ; s++) {
                const float nxt = (s + 1 < SEQ) ? __ldg(&xs[(s + 1) * INC + c]) : 0.0f;
                o[s] = fmaf(w0, prev, o[s]);
                o[s] = fmaf(w1, cur,  o[s]);
                o[s] = fmaf(w2, nxt,  o[s]);
                prev = cur; cur = nxt;
            }
        }
#pragma unroll
        for (int s = 0; s < SEQ; s++) {
            const float v  = o[s];
            const float sg = __fdividef(1.0f, 1.0f + __expf(-v));
            sC[sp * SC_STRIDE + k * SEQ + s] = v * sg;
        }
    }
    __syncthreads();

    // ---- enc1: [1440 -> 128] + ReLU, 8 samples per thread ----
    {
        const int oc   = tid & 127;
        const int half = tid >> 7;
        float a[8];
        const float b0 = __ldg(&enc1_b[oc]);
#pragma unroll
        for (int s = 0; s < 8; s++) a[s] = b0;
        const float* cbase = sC + (half * 8) * SC_STRIDE;

        for (int i0 = 0; i0 < FLAT; i0 += 32) {
            __syncthreads();
            for (int l = tid; l < 128 * 32; l += 256) {
                const int r  = l >> 5;
                const int ii = l & 31;
                sW[r * SW_STRIDE + ii] = __ldg(&enc1_w[(size_t)r * FLAT + i0 + ii]);
            }
            __syncthreads();
#pragma unroll
            for (int ii = 0; ii < 32; ii += 4) {
                const float4 w = *(const float4*)(sW + oc * SW_STRIDE + ii);
#pragma unroll
                for (int s = 0; s < 8; s++) {
                    const float4 v = *(const float4*)(cbase + s * SC_STRIDE + i0 + ii);
                    a[s] = fmaf(w.x, v.x, fmaf(w.y, v.y, fmaf(w.z, v.z, fmaf(w.w, v.w, a[s]))));
                }
            }
        }
#pragma unroll
        for (int s = 0; s < 8; s++)
            sH1[(half * 8 + s) * 128 + oc] = fmaxf(a[s], 0.0f);
    }
    __syncthreads();

    // ---- enc2: [128 -> 64] -> g_theta0 TRANSPOSED [dim][sample] ----
    float* gT = (float*)g_theta0;
    for (int t = tid; t < ENC_SPB * HID; t += 256) {
        const int sp = t >> 6;
        const int oc = t & 63;
        float acc = __ldg(&enc2_b[oc]);
        const float* wr = enc2_w + oc * 128;
        const float* hv = sH1 + sp * 128;
#pragma unroll
        for (int i = 0; i < 128; i += 4) {
            const float4 wv = __ldg((const float4*)(wr + i));
            const float4 h4 = *(const float4*)(hv + i);
            acc = fmaf(wv.x, h4.x, fmaf(wv.y, h4.y, fmaf(wv.z, h4.z, fmaf(wv.w, h4.w, acc))));
        }
        gT[(size_t)oc * B + (blk * ENC_SPB + sp)] = acc;
    }
}

// ================================ ODE ======================================
// 32 samples per CTA (16 pairs), 128 threads / 4 warps.
// Warp w: dim band [16w,16w+16) x all 16 pairs.
// Lane: ps = l&7 (pairs 2ps,2ps+1), dg = l>>3; thread dims = 16w + j*4 + dg.
#define ODE_SPB 32
#define AST 18                       // activation ull row stride
#define WST 68                       // weight float row stride (%32==4)
#define ODE_SMEM_BYTES (2*HID*AST*8 + 2*HID*WST*4 + 2*HID*4)

__device__ __forceinline__ void matvec42(
    const float* __restrict__ sW, const float* __restrict__ sb,
    const ull* __restrict__ sIn,
    const int wband, const int dg, const int ps2, ull (&acc)[4][2])
{
#pragma unroll
    for (int j = 0; j < 4; j++) {
        const ull b = dup2(sb[wband + j * 4 + dg]);
        acc[j][0] = b; acc[j][1] = b;
    }
#pragma unroll
    for (int i = 0; i < HID; i += 4) {
        const ulonglong2 y0 = *(const ulonglong2*)(sIn + (i + 0) * AST + ps2);
        const ulonglong2 y1 = *(const ulonglong2*)(sIn + (i + 1) * AST + ps2);
        const ulonglong2 y2 = *(const ulonglong2*)(sIn + (i + 2) * AST + ps2);
        const ulonglong2 y3 = *(const ulonglong2*)(sIn + (i + 3) * AST + ps2);
#pragma unroll
        for (int j = 0; j < 4; j++) {
            const float4 w = *(const float4*)(sW + (wband + j * 4 + dg) * WST + i);
            const ull w0 = dup2(w.x), w1 = dup2(w.y), w2 = dup2(w.z), w3 = dup2(w.w);
            acc[j][0] = fma2(w0, y0.x, acc[j][0]);  acc[j][1] = fma2(w0, y0.y, acc[j][1]);
            acc[j][0] = fma2(w1, y1.x, acc[j][0]);  acc[j][1] = fma2(w1, y1.y, acc[j][1]);
            acc[j][0] = fma2(w2, y2.x, acc[j][0]);  acc[j][1] = fma2(w2, y2.y, acc[j][1]);
            acc[j][0] = fma2(w3, y3.x, acc[j][0]);  acc[j][1] = fma2(w3, y3.y, acc[j][1]);
        }
    }
}

// full f(y): sA -> k ; clobbers sB; one internal barrier
__device__ __forceinline__ void eval_f(
    const float* __restrict__ sW1, const float* __restrict__ sW2,
    const float* __restrict__ sb1, const float* __restrict__ sb2,
    const ull* __restrict__ sA, ull* __restrict__ sB,
    const int wband, const int dg, const int ps2, ull (&k)[4][2])
{
    ull acc[4][2];
    matvec42(sW1, sb1, sA, wband, dg, ps2, acc);
#pragma unroll
    for (int j = 0; j < 4; j++) {
        ulonglong2 t; t.x = tanh2(acc[j][0]); t.y = tanh2(acc[j][1]);
        *(ulonglong2*)(sB + (wband + j * 4 + dg) * AST + ps2) = t;
    }
    __syncthreads();
    matvec42(sW2, sb2, sB, wband, dg, ps2, k);
}

#define STORE_SA(arr)                                                          \
    do {                                                                       \
        _Pragma("unroll")                                                      \
        for (int j = 0; j < 4; j++) {                                          \
            ulonglong2 t; t.x = (arr)[j][0]; t.y = (arr)[j][1];                \
            *(ulonglong2*)(sA + (wband + j * 4 + dg) * AST + ps2) = t;         \
        }                                                                      \
    } while (0)

__global__ void __launch_bounds__(128, 3) ode_kernel(
    const float* __restrict__ t_span,
    const float* __restrict__ w1g, const float* __restrict__ b1g,
    const float* __restrict__ w2g, const float* __restrict__ b2g,
    const float* __restrict__ r1w, const float* __restrict__ r1b,
    const float* __restrict__ r2w, const float* __restrict__ r2b,
    float* __restrict__ out, int B)
{
    extern __shared__ char smraw[];
    ull*   sA  = (ull*)smraw;              // [64][AST]
    ull*   sB  = sA + HID * AST;           // [64][AST]
    float* sW1 = (float*)(sB + HID * AST); // [64][WST]
    float* sW2 = sW1 + HID * WST;
    float* sb1 = sW2 + HID * WST;          // [64]
    float* sb2 = sb1 + HID;

    const int tid   = threadIdx.x;
    const int w     = tid >> 5;
    const int l     = tid & 31;
    const int ps    = l & 7;
    const int dg    = l >> 3;
    const int wband = w * 16;
    const int ps2   = ps * 2;

    for (int i = tid; i < HID * HID; i += 128) {
        const int r = i >> 6, c = i & 63;
        sW1[r * WST + c] = w1g[i];
        sW2[r * WST + c] = w2g[i];
    }
    if (tid < HID) { sb1[tid] = b1g[tid]; sb2[tid] = b2g[tid]; }

    const float dt = (__ldg(&t_span[1]) - __ldg(&t_span[0])) * (1.0f / STEPS);

    // init: y regs + sA from transposed theta0
    const int PS = B >> 1;
    const int pairBase = blockIdx.x * (ODE_SPB / 2);
    ull y[4][2];
#pragma unroll
    for (int j = 0; j < 4; j++) {
        const int d = wband + j * 4 + dg;
        y[j][0] = g_theta0[(size_t)d * PS + pairBase + ps2];
        y[j][1] = g_theta0[(size_t)d * PS + pairBase + ps2 + 1];
    }
    STORE_SA(y);

    ull k1[4][2], k2[4][2], k3[4][2], k4[4][2], k5[4][2];

    for (int step = 0; step < STEPS; step++) {
        __syncthreads();
        eval_f(sW1, sW2, sb1, sb2, sA, sB, wband, dg, ps2, k1);
        {
            const ull c1 = dup2(dt * 0.2f);
            ull nv[4][2];
#pragma unroll
            for (int j = 0; j < 4; j++)
#pragma unroll
                for (int h = 0; h < 2; h++)
                    nv[j][h] = fma2(c1, k1[j][h], y[j][h]);
            __syncthreads();
            STORE_SA(nv);
        }
        __syncthreads();
        eval_f(sW1, sW2, sb1, sb2, sA, sB, wband, dg, ps2, k2);
        {
            const ull c1 = dup2(dt * (3.0f / 40.0f)), c2 = dup2(dt * (9.0f / 40.0f));
            ull nv[4][2];
#pragma unroll
            for (int j = 0; j < 4; j++)
#pragma unroll
                for (int h = 0; h < 2; h++)
                    nv[j][h] = fma2(c1, k1[j][h], fma2(c2, k2[j][h], y[j][h]));
            __syncthreads();
            STORE_SA(nv);
        }
        __syncthreads();
        eval_f(sW1, sW2, sb1, sb2, sA, sB, wband, dg, ps2, k3);
        {
            const ull c1 = dup2(dt * (44.0f / 45.0f)), c2 = dup2(dt * (-56.0f / 15.0f)),
                      c3 = dup2(dt * (32.0f / 9.0f));
            ull nv[4][2];
#pragma unroll
            for (int j = 0; j < 4; j++)
#pragma unroll
                for (int h = 0; h < 2; h++)
                    nv[j][h] = fma2(c1, k1[j][h], fma2(c2, k2[j][h],
                               fma2(c3, k3[j][h], y[j][h])));
            __syncthreads();
            STORE_SA(nv);
        }
        __syncthreads();
        eval_f(sW1, sW2, sb1, sb2, sA, sB, wband, dg, ps2, k4);
        {
            const ull c1 = dup2(dt * (19372.0f / 6561.0f)), c2 = dup2(dt * (-25360.0f / 2187.0f)),
                      c3 = dup2(dt * (64448.0f / 6561.0f)), c4 = dup2(dt * (-212.0f / 729.0f));
            ull nv[4][2];
#pragma unroll
            for (int j = 0; j < 4; j++)
#pragma unroll
                for (int h = 0; h < 2; h++)
                    nv[j][h] = fma2(c1, k1[j][h], fma2(c2, k2[j][h], fma2(c3, k3[j][h],
                               fma2(c4, k4[j][h], y[j][h]))));
            __syncthreads();
            STORE_SA(nv);
        }
        __syncthreads();
        eval_f(sW1, sW2, sb1, sb2, sA, sB, wband, dg, ps2, k5);
        {
            const ull c1 = dup2(dt * (9017.0f / 3168.0f)), c2 = dup2(dt * (-355.0f / 33.0f)),
                      c3 = dup2(dt * (46732.0f / 5247.0f)), c4 = dup2(dt * (49.0f / 176.0f)),
                      c5 = dup2(dt * (-5103.0f / 18656.0f));
            ull nv[4][2];
#pragma unroll
            for (int j = 0; j < 4; j++)
#pragma unroll
                for (int h = 0; h < 2; h++)
                    nv[j][h] = fma2(c1, k1[j][h], fma2(c2, k2[j][h], fma2(c3, k3[j][h],
                               fma2(c4, k4[j][h], fma2(c5, k5[j][h], y[j][h])))));
            __syncthreads();
            STORE_SA(nv);
        }
        __syncthreads();
        {
            ull k6[4][2];
            eval_f(sW1, sW2, sb1, sb2, sA, sB, wband, dg, ps2, k6);
            const ull b1 = dup2(dt * (35.0f / 384.0f)),  b3 = dup2(dt * (500.0f / 1113.0f)),
                      b4 = dup2(dt * (125.0f / 192.0f)), b5 = dup2(dt * (-2187.0f / 6784.0f)),
                      b6 = dup2(dt * (11.0f / 84.0f));
#pragma unroll
            for (int j = 0; j < 4; j++)
#pragma unroll
                for (int h = 0; h < 2; h++)
                    y[j][h] = fma2(b1, k1[j][h], fma2(b3, k3[j][h], fma2(b4, k4[j][h],
                              fma2(b5, k5[j][h], fma2(b6, k6[j][h], y[j][h])))));
            __syncthreads();
            STORE_SA(y);
        }
    }
    __syncthreads();

    // ---- regressor: 4 threads per sample, 8 reg1 rows each ----
    {
        const int s  = tid >> 2;              // local sample 0..31
        const int mg = (tid & 3) * 8;
        const int pr = s >> 1, hb = s & 1;
        float accm[8];
#pragma unroll
        for (int m = 0; m < 8; m++) accm[m] = __ldg(&r1b[mg + m]);
        for (int i = 0; i < HID; i++) {
            const float2 yv = un2(sA[i * AST + pr]);
            const float  yy = hb ? yv.y : yv.x;
#pragma unroll
            for (int m = 0; m < 8; m++)
                accm[m] = fmaf(__ldg(&r1w[(mg + m) * HID + i]), yy, accm[m]);
        }
        float part = 0.0f;
#pragma unroll
        for (int m = 0; m < 8; m++)
            part = fmaf(__ldg(&r2w[mg + m]), fmaxf(accm[m], 0.0f), part);
        part += __shfl_xor_sync(0xffffffffu, part, 1);
        part += __shfl_xor_sync(0xffffffffu, part, 2);
        if ((tid & 3) == 0)
            out[(long long)blockIdx.x * ODE_SPB + s] = part + __ldg(&r2b[0]);
    }
}

// ============================== launch ======================================
extern "C" void kernel_launch(void* const* d_in, const int* in_sizes, int n_in,
                              void* d_out, int out_size)
{
    const float* x      = (const float*)d_in[0];
    const float* t_span = (const float*)d_in[1];
    const float* conv_w = (const float*)d_in[2];
    const float* conv_b = (const float*)d_in[3];
    const float* enc1_w = (const float*)d_in[4];
    const float* enc1_b = (const float*)d_in[5];
    const float* enc2_w = (const float*)d_in[6];
    const float* enc2_b = (const float*)d_in[7];
    const float* ode1_w = (const float*)d_in[8];
    const float* ode1_b = (const float*)d_in[9];
    const float* ode2_w = (const float*)d_in[10];
    const float* ode2_b = (const float*)d_in[11];
    const float* reg1_w = (const float*)d_in[12];
    const float* reg1_b = (const float*)d_in[13];
    const float* reg2_w = (const float*)d_in[14];
    const float* reg2_b = (const float*)d_in[15];
    float* out = (float*)d_out;

    const int B = in_sizes[0] / (SEQ * INC);

    const int enc_smem = ENC_SMEM_FLOATS * (int)sizeof(float);
    const int ode_smem = ODE_SMEM_BYTES;
    cudaFuncSetAttribute(enc_kernel, cudaFuncAttributeMaxDynamicSharedMemorySize, enc_smem);
    cudaFuncSetAttribute(ode_kernel, cudaFuncAttributeMaxDynamicSharedMemorySize, ode_smem);

    enc_kernel<<<B / ENC_SPB, 256, enc_smem>>>(
        x, conv_w, conv_b, enc1_w, enc1_b, enc2_w, enc2_b, B);
    ode_kernel<<<B / ODE_SPB, 128, ode_smem>>>(
        t_span, ode1_w, ode1_b, ode2_w, ode2_b,
        reg1_w, reg1_b, reg2_w, reg2_b, out, B);
}

// round 8
// speedup vs baseline: 4.1043x; 1.9304x over previous
#include <cuda_runtime.h>
#include <cuda_bf16.h>

// ---------------------------------------------------------------------------
// CNN_ODE: conv1d+SiLU -> MLP encoder -> 50-step fixed dopri5 (64-dim neural
// ODE, tf32 tensor cores) -> regressor.  B = 65536 independent samples.
// ---------------------------------------------------------------------------

#define SEQ   40
#define INC   24
#define NK    36
#define FLAT  1440
#define HID   64
#define STEPS 50

// theta0 scratch, TRANSPOSED: [dim][sample], float
__device__ float g_theta0[HID * 65536];   // 16 MB

__device__ __forceinline__ float tanhap(float x) {
    float r; asm("tanh.approx.f32 %0,%1;" : "=f"(r) : "f"(x)); return r;
}
__device__ __forceinline__ unsigned f2tf(float f) {
    unsigned u; asm("cvt.rna.tf32.f32 %0,%1;" : "=r"(u) : "f"(f)); return u;
}

// ============================== Encoder ====================================
#define ENC_SPB    16
#define SC_STRIDE  1444
#define SW_STRIDE  36
#define ENC_SMEM_FLOATS (ENC_SPB*SC_STRIDE + ENC_SPB*128 + 128*SW_STRIDE)

__global__ void __launch_bounds__(256) enc_kernel(
    const float* __restrict__ x,
    const float* __restrict__ conv_w, const float* __restrict__ conv_b,
    const float* __restrict__ enc1_w, const float* __restrict__ enc1_b,
    const float* __restrict__ enc2_w, const float* __restrict__ enc2_b,
    int B)
{
    extern __shared__ float sm[];
    float* sC  = sm;                                // [16][SC_STRIDE]
    float* sH1 = sC  + ENC_SPB * SC_STRIDE;         // [16][128]
    float* sW  = sH1 + ENC_SPB * 128;               // [128][36]

    const int tid = threadIdx.x;
    const long long blk = blockIdx.x;

    // ---- conv1d (pad=1) + SiLU -> sC (flatten order k*SEQ + s) ----
    for (int t = tid; t < NK * ENC_SPB; t += 256) {
        const int k  = t % NK;
        const int sp = t / NK;
        const float* xs = x + (blk * ENC_SPB + sp) * (SEQ * INC);
        float o[SEQ];
        const float bk = __ldg(&conv_b[k]);
#pragma unroll
        for (int s = 0; s < SEQ; s++) o[s] = bk;
        for (int c = 0; c < INC; c++) {
            const float w0 = __ldg(&conv_w[k * 72 + c * 3 + 0]);
            const float w1 = __ldg(&conv_w[k * 72 + c * 3 + 1]);
            const float w2 = __ldg(&conv_w[k * 72 + c * 3 + 2]);
            float prev = 0.0f;
            float cur  = __ldg(&xs[0 * INC + c]);
#pragma unroll
            for (int s = 0; s < SEQ; s++) {
                const float nxt = (s + 1 < SEQ) ? __ldg(&xs[(s + 1) * INC + c]) : 0.0f;
                o[s] = fmaf(w0, prev, o[s]);
                o[s] = fmaf(w1, cur,  o[s]);
                o[s] = fmaf(w2, nxt,  o[s]);
                prev = cur; cur = nxt;
            }
        }
#pragma unroll
        for (int s = 0; s < SEQ; s++) {
            const float v  = o[s];
            const float sg = __fdividef(1.0f, 1.0f + __expf(-v));
            sC[sp * SC_STRIDE + k * SEQ + s] = v * sg;
        }
    }
    __syncthreads();

    // ---- enc1: [1440 -> 128] + ReLU, 8 samples per thread ----
    {
        const int oc   = tid & 127;
        const int half = tid >> 7;
        float a[8];
        const float b0 = __ldg(&enc1_b[oc]);
#pragma unroll
        for (int s = 0; s < 8; s++) a[s] = b0;
        const float* cbase = sC + (half * 8) * SC_STRIDE;

        for (int i0 = 0; i0 < FLAT; i0 += 32) {
            __syncthreads();
            for (int l = tid; l < 128 * 32; l += 256) {
                const int r  = l >> 5;
                const int ii = l & 31;
                sW[r * SW_STRIDE + ii] = __ldg(&enc1_w[(size_t)r * FLAT + i0 + ii]);
            }
            __syncthreads();
#pragma unroll
            for (int ii = 0; ii < 32; ii += 4) {
                const float4 w = *(const float4*)(sW + oc * SW_STRIDE + ii);
#pragma unroll
                for (int s = 0; s < 8; s++) {
                    const float4 v = *(const float4*)(cbase + s * SC_STRIDE + i0 + ii);
                    a[s] = fmaf(w.x, v.x, fmaf(w.y, v.y, fmaf(w.z, v.z, fmaf(w.w, v.w, a[s]))));
                }
            }
        }
#pragma unroll
        for (int s = 0; s < 8; s++)
            sH1[(half * 8 + s) * 128 + oc] = fmaxf(a[s], 0.0f);
    }
    __syncthreads();

    // ---- enc2: [128 -> 64] -> g_theta0 TRANSPOSED [dim][sample] ----
    for (int t = tid; t < ENC_SPB * HID; t += 256) {
        const int sp = t >> 6;
        const int oc = t & 63;
        float acc = __ldg(&enc2_b[oc]);
        const float* wr = enc2_w + oc * 128;
        const float* hv = sH1 + sp * 128;
#pragma unroll
        for (int i = 0; i < 128; i += 4) {
            const float4 wv = __ldg((const float4*)(wr + i));
            const float4 h4 = *(const float4*)(hv + i);
            acc = fmaf(wv.x, h4.x, fmaf(wv.y, h4.y, fmaf(wv.z, h4.z, fmaf(wv.w, h4.w, acc))));
        }
        g_theta0[(size_t)oc * B + (blk * ENC_SPB + sp)] = acc;
    }
}

// ================================ ODE ======================================
// 32 samples/CTA, 256 threads = 8 warps. Warp w: mw = w&3 (16 dims), nh = w>>2
// (16 samples).  mma.sync.m16n8k8 tf32, W1/W2 as A-fragments in registers.
#define ODE_SPB 32
#define ST 40                              // sY/sH row stride (floats)

__device__ __forceinline__ void mma_tf32(
    float (&c)[4], const unsigned (&a)[4], unsigned b0, unsigned b1)
{
    asm("mma.sync.aligned.m16n8k8.row.col.f32.tf32.tf32.f32 "
        "{%0,%1,%2,%3},{%4,%5,%6,%7},{%8,%9},{%0,%1,%2,%3};"
        : "+f"(c[0]), "+f"(c[1]), "+f"(c[2]), "+f"(c[3])
        : "r"(a[0]), "r"(a[1]), "r"(a[2]), "r"(a[3]), "r"(b0), "r"(b1));
}

// c[nt] = bias + W * in  (in: tf32 bits in SMEM, [64][ST])
__device__ __forceinline__ void gemm16x16(
    const unsigned (&A)[8][4], const unsigned* __restrict__ sIn,
    float blo, float bhi, int nbase, int g, int tig, float (&c)[2][4])
{
#pragma unroll
    for (int nt = 0; nt < 2; nt++) {
        c[nt][0] = blo; c[nt][1] = blo; c[nt][2] = bhi; c[nt][3] = bhi;
    }
#pragma unroll
    for (int kt = 0; kt < 8; kt++) {
        const int a0 = (kt * 8 + tig) * ST + nbase + g;
        const int a1 = a0 + 4 * ST;
#pragma unroll
        for (int nt = 0; nt < 2; nt++) {
            const unsigned b0 = sIn[a0 + nt * 8];
            const unsigned b1 = sIn[a1 + nt * 8];
            mma_tf32(c[nt], A[kt], b0, b1);
        }
    }
}

// store a C-layout fragment pair (rows m0/m0+8, cols n0,n0+1) as tf32 bits
__device__ __forceinline__ void store_frag_tf32(
    unsigned* __restrict__ dst, const float (&c)[2][4],
    int m0, int nbase, int tig)
{
#pragma unroll
    for (int nt = 0; nt < 2; nt++) {
        const int n0 = nbase + nt * 8 + 2 * tig;
        uint2 lo; lo.x = f2tf(c[nt][0]); lo.y = f2tf(c[nt][1]);
        uint2 hi; hi.x = f2tf(c[nt][2]); hi.y = f2tf(c[nt][3]);
        *(uint2*)(dst + m0 * ST + n0)       = lo;
        *(uint2*)(dst + (m0 + 8) * ST + n0) = hi;
    }
}

// full f: sY -> k frags (uses sH scratch; 1 internal barrier)
__device__ __forceinline__ void eval_f(
    const unsigned (&A1)[8][4], const unsigned (&A2)[8][4],
    float b1lo, float b1hi, float b2lo, float b2hi,
    const unsigned* __restrict__ sY, unsigned* __restrict__ sH,
    int m0, int nbase, int g, int tig, float (&k)[2][4])
{
    float h[2][4];
    gemm16x16(A1, sY, b1lo, b1hi, nbase, g, tig, h);
#pragma unroll
    for (int nt = 0; nt < 2; nt++)
#pragma unroll
        for (int e = 0; e < 4; e++) h[nt][e] = tanhap(h[nt][e]);
    store_frag_tf32(sH, h, m0, nbase, tig);
    __syncthreads();
    gemm16x16(A2, sH, b2lo, b2hi, nbase, g, tig, k);
}

__global__ void __launch_bounds__(256) ode_kernel(
    const float* __restrict__ t_span,
    const float* __restrict__ w1g, const float* __restrict__ b1g,
    const float* __restrict__ w2g, const float* __restrict__ b2g,
    const float* __restrict__ r1w, const float* __restrict__ r1b,
    const float* __restrict__ r2w, const float* __restrict__ r2b,
    float* __restrict__ out, int B)
{
    __shared__ unsigned sY[HID * ST];      // stage input (tf32 bits / f32 at end)
    __shared__ unsigned sH[HID * ST];      // tanh hidden (tf32 bits)

    const int tid  = threadIdx.x;
    const int w    = tid >> 5;
    const int lane = tid & 31;
    const int g    = lane >> 2;            // groupID
    const int tig  = lane & 3;             // thread-in-group
    const int mw   = w & 3;
    const int nh   = w >> 2;
    const int m0   = mw * 16 + g;          // fragment row (and m0+8)
    const int nbase = nh * 16;

    // ---- load W1/W2 as A fragments (tf32), biases ----
    unsigned A1[8][4], A2[8][4];
#pragma unroll
    for (int kt = 0; kt < 8; kt++) {
        const int k0 = kt * 8 + tig;
        A1[kt][0] = f2tf(__ldg(&w1g[(m0)     * HID + k0]));
        A1[kt][1] = f2tf(__ldg(&w1g[(m0 + 8) * HID + k0]));
        A1[kt][2] = f2tf(__ldg(&w1g[(m0)     * HID + k0 + 4]));
        A1[kt][3] = f2tf(__ldg(&w1g[(m0 + 8) * HID + k0 + 4]));
        A2[kt][0] = f2tf(__ldg(&w2g[(m0)     * HID + k0]));
        A2[kt][1] = f2tf(__ldg(&w2g[(m0 + 8) * HID + k0]));
        A2[kt][2] = f2tf(__ldg(&w2g[(m0)     * HID + k0 + 4]));
        A2[kt][3] = f2tf(__ldg(&w2g[(m0 + 8) * HID + k0 + 4]));
    }
    const float b1lo = __ldg(&b1g[m0]), b1hi = __ldg(&b1g[m0 + 8]);
    const float b2lo = __ldg(&b2g[m0]), b2hi = __ldg(&b2g[m0 + 8]);

    const float dt = (__ldg(&t_span[1]) - __ldg(&t_span[0])) * (1.0f / STEPS);

    // ---- init y frags from g_theta0 [dim][sample] ----
    const long long gbase = (long long)blockIdx.x * ODE_SPB;
    float y[2][4];
#pragma unroll
    for (int nt = 0; nt < 2; nt++) {
        const long long n0 = gbase + nbase + nt * 8 + 2 * tig;
        y[nt][0] = __ldg(&g_theta0[(size_t)m0 * B + n0]);
        y[nt][1] = __ldg(&g_theta0[(size_t)m0 * B + n0 + 1]);
        y[nt][2] = __ldg(&g_theta0[(size_t)(m0 + 8) * B + n0]);
        y[nt][3] = __ldg(&g_theta0[(size_t)(m0 + 8) * B + n0 + 1]);
    }
    store_frag_tf32(sY, y, m0, nbase, tig);
    __syncthreads();

    float k1[2][4], k2[2][4], k3[2][4], k4[2][4], k5[2][4], k6[2][4], nv[2][4];

#define ELEM_LOOP(expr)                                                        \
    _Pragma("unroll") for (int nt = 0; nt < 2; nt++)                           \
    _Pragma("unroll") for (int e = 0; e < 4; e++) { expr; }

    for (int step = 0; step < STEPS; step++) {
        eval_f(A1, A2, b1lo, b1hi, b2lo, b2hi, sY, sH, m0, nbase, g, tig, k1);
        __syncthreads();
        {
            const float c1 = dt * 0.2f;
            ELEM_LOOP(nv[nt][e] = fmaf(c1, k1[nt][e], y[nt][e]));
            store_frag_tf32(sY, nv, m0, nbase, tig);
        }
        __syncthreads();
        eval_f(A1, A2, b1lo, b1hi, b2lo, b2hi, sY, sH, m0, nbase, g, tig, k2);
        __syncthreads();
        {
            const float c1 = dt * (3.0f / 40.0f), c2 = dt * (9.0f / 40.0f);
            ELEM_LOOP(nv[nt][e] = fmaf(c1, k1[nt][e], fmaf(c2, k2[nt][e], y[nt][e])));
            store_frag_tf32(sY, nv, m0, nbase, tig);
        }
        __syncthreads();
        eval_f(A1, A2, b1lo, b1hi, b2lo, b2hi, sY, sH, m0, nbase, g, tig, k3);
        __syncthreads();
        {
            const float c1 = dt * (44.0f / 45.0f), c2 = dt * (-56.0f / 15.0f),
                        c3 = dt * (32.0f / 9.0f);
            ELEM_LOOP(nv[nt][e] = fmaf(c1, k1[nt][e], fmaf(c2, k2[nt][e],
                                  fmaf(c3, k3[nt][e], y[nt][e]))));
            store_frag_tf32(sY, nv, m0, nbase, tig);
        }
        __syncthreads();
        eval_f(A1, A2, b1lo, b1hi, b2lo, b2hi, sY, sH, m0, nbase, g, tig, k4);
        __syncthreads();
        {
            const float c1 = dt * (19372.0f / 6561.0f), c2 = dt * (-25360.0f / 2187.0f),
                        c3 = dt * (64448.0f / 6561.0f), c4 = dt * (-212.0f / 729.0f);
            ELEM_LOOP(nv[nt][e] = fmaf(c1, k1[nt][e], fmaf(c2, k2[nt][e],
                                  fmaf(c3, k3[nt][e], fmaf(c4, k4[nt][e], y[nt][e])))));
            store_frag_tf32(sY, nv, m0, nbase, tig);
        }
        __syncthreads();
        eval_f(A1, A2, b1lo, b1hi, b2lo, b2hi, sY, sH, m0, nbase, g, tig, k5);
        __syncthreads();
        {
            const float c1 = dt * (9017.0f / 3168.0f), c2 = dt * (-355.0f / 33.0f),
                        c3 = dt * (46732.0f / 5247.0f), c4 = dt * (49.0f / 176.0f),
                        c5 = dt * (-5103.0f / 18656.0f);
            ELEM_LOOP(nv[nt][e] = fmaf(c1, k1[nt][e], fmaf(c2, k2[nt][e],
                                  fmaf(c3, k3[nt][e], fmaf(c4, k4[nt][e],
                                  fmaf(c5, k5[nt][e], y[nt][e]))))));
            store_frag_tf32(sY, nv, m0, nbase, tig);
        }
        __syncthreads();
        eval_f(A1, A2, b1lo, b1hi, b2lo, b2hi, sY, sH, m0, nbase, g, tig, k6);
        __syncthreads();
        {
            const float c1 = dt * (35.0f / 384.0f),  c3 = dt * (500.0f / 1113.0f),
                        c4 = dt * (125.0f / 192.0f), c5 = dt * (-2187.0f / 6784.0f),
                        c6 = dt * (11.0f / 84.0f);
            ELEM_LOOP(y[nt][e] = fmaf(c1, k1[nt][e], fmaf(c3, k3[nt][e],
                                 fmaf(c4, k4[nt][e], fmaf(c5, k5[nt][e],
                                 fmaf(c6, k6[nt][e], y[nt][e]))))));
            store_frag_tf32(sY, y, m0, nbase, tig);
        }
        __syncthreads();
    }

    // overwrite sY with full-precision y for the regressor
#pragma unroll
    for (int nt = 0; nt < 2; nt++) {
        const int n0 = nbase + nt * 8 + 2 * tig;
        float* sYf = (float*)sY;
        sYf[m0 * ST + n0]           = y[nt][0];
        sYf[m0 * ST + n0 + 1]       = y[nt][1];
        sYf[(m0 + 8) * ST + n0]     = y[nt][2];
        sYf[(m0 + 8) * ST + n0 + 1] = y[nt][3];
    }
    __syncthreads();

    // ---- regressor: threads 0..127, 4 per sample ----
    if (tid < 128) {
        const float* sYf = (const float*)sY;
        const int s  = tid >> 2;               // 0..31
        const int mg = (tid & 3) * 8;
        float accm[8];
#pragma unroll
        for (int m = 0; m < 8; m++) accm[m] = __ldg(&r1b[mg + m]);
        for (int i = 0; i < HID; i++) {
            const float yy = sYf[i * ST + s];
#pragma unroll
            for (int m = 0; m < 8; m++)
                accm[m] = fmaf(__ldg(&r1w[(mg + m) * HID + i]), yy, accm[m]);
        }
        float part = 0.0f;
#pragma unroll
        for (int m = 0; m < 8; m++)
            part = fmaf(__ldg(&r2w[mg + m]), fmaxf(accm[m], 0.0f), part);
        part += __shfl_xor_sync(0xffffffffu, part, 1);
        part += __shfl_xor_sync(0xffffffffu, part, 2);
        if ((tid & 3) == 0)
            out[(long long)blockIdx.x * ODE_SPB + s] = part + __ldg(&r2b[0]);
    }
}

// ============================== launch ======================================
extern "C" void kernel_launch(void* const* d_in, const int* in_sizes, int n_in,
                              void* d_out, int out_size)
{
    const float* x      = (const float*)d_in[0];
    const float* t_span = (const float*)d_in[1];
    const float* conv_w = (const float*)d_in[2];
    const float* conv_b = (const float*)d_in[3];
    const float* enc1_w = (const float*)d_in[4];
    const float* enc1_b = (const float*)d_in[5];
    const float* enc2_w = (const float*)d_in[6];
    const float* enc2_b = (const float*)d_in[7];
    const float* ode1_w = (const float*)d_in[8];
    const float* ode1_b = (const float*)d_in[9];
    const float* ode2_w = (const float*)d_in[10];
    const float* ode2_b = (const float*)d_in[11];
    const float* reg1_w = (const float*)d_in[12];
    const float* reg1_b = (const float*)d_in[13];
    const float* reg2_w = (const float*)d_in[14];
    const float* reg2_b = (const float*)d_in[15];
    float* out = (float*)d_out;

    const int B = in_sizes[0] / (SEQ * INC);

    const int enc_smem = ENC_SMEM_FLOATS * (int)sizeof(float);
    cudaFuncSetAttribute(enc_kernel, cudaFuncAttributeMaxDynamicSharedMemorySize, enc_smem);

    enc_kernel<<<B / ENC_SPB, 256, enc_smem>>>(
        x, conv_w, conv_b, enc1_w, enc1_b, enc2_w, enc2_b, B);
    ode_kernel<<<B / ODE_SPB, 256>>>(
        t_span, ode1_w, ode1_b, ode2_w, ode2_b,
        reg1_w, reg1_b, reg2_w, reg2_b, out, B);
}

// round 9
// speedup vs baseline: 6.4678x; 1.5759x over previous
#include <cuda_runtime.h>
#include <cuda_bf16.h>

// ---------------------------------------------------------------------------
// CNN_ODE: conv1d+SiLU -> MLP encoder (tf32 mma) -> 50-step fixed dopri5
// (64-dim neural ODE, tf32 mma) -> regressor.  B = 65536 samples.
// ---------------------------------------------------------------------------

#define SEQ   40
#define INC   24
#define NK    36
#define FLAT  1440
#define HID   64
#define STEPS 50

// theta0 scratch, TRANSPOSED: [dim][sample], float
__device__ float g_theta0[HID * 65536];   // 16 MB

__device__ __forceinline__ float tanhap(float x) {
    float r; asm("tanh.approx.f32 %0,%1;" : "=f"(r) : "f"(x)); return r;
}
__device__ __forceinline__ unsigned f2tf(float f) {
    unsigned u; asm("cvt.rna.tf32.f32 %0,%1;" : "=r"(u) : "f"(f)); return u;
}
__device__ __forceinline__ void mma_tf32(
    float (&c)[4], const unsigned (&a)[4], unsigned b0, unsigned b1)
{
    asm("mma.sync.aligned.m16n8k8.row.col.f32.tf32.tf32.f32 "
        "{%0,%1,%2,%3},{%4,%5,%6,%7},{%8,%9},{%0,%1,%2,%3};"
        : "+f"(c[0]), "+f"(c[1]), "+f"(c[2]), "+f"(c[3])
        : "r"(a[0]), "r"(a[1]), "r"(a[2]), "r"(a[3]), "r"(b0), "r"(b1));
}

// ============================== Encoder ====================================
// 32 samples/CTA, 256 threads.
//  conv (SIMT, x staged in regs, two c-halves) -> sC tf32 [32][1444]
//  enc1: tf32 mma, M=32 samples x N=128 out x K=1440 (weights streamed)
//  enc2: SIMT [128->64] -> g_theta0 transposed
#define ENC_SPB 32
#define SCST    1444                     // sC row stride (uints); %32==4
#define SWST    36                       // weight chunk row stride; %32==4
#define SH1ST   132                      // sH1 row stride; %32==4
#define ENC_SMEM_BYTES ((ENC_SPB*SCST + 128*SWST + ENC_SPB*SH1ST) * 4)

__global__ void __launch_bounds__(256) enc_kernel(
    const float* __restrict__ x,
    const float* __restrict__ conv_w, const float* __restrict__ conv_b,
    const float* __restrict__ enc1_w, const float* __restrict__ enc1_b,
    const float* __restrict__ enc2_w, const float* __restrict__ enc2_b,
    int B)
{
    extern __shared__ unsigned smu[];
    unsigned* sC  = smu;                          // [32][SCST]
    unsigned* sW  = sC + ENC_SPB * SCST;          // [128][SWST]
    float*    sH1 = (float*)(sW + 128 * SWST);    // [32][SH1ST]

    const int tid = threadIdx.x;
    const long long blk = blockIdx.x;

    // ---- stage conv weights into sH1 area (free until enc1 output) ----
    float* scw = sH1;                             // 2592 floats
    for (int i = tid; i < NK * 72; i += 256) scw[i] = conv_w[i];
    __syncthreads();

    // ---- conv1d (pad=1): thread = (sample, 5-wide s-range), two c-halves ----
    {
        const int sp = tid >> 3;                  // 0..31
        const int sq = tid & 7;                   // s-range [5sq, 5sq+5)
        const float* xs = x + (blk * ENC_SPB + sp) * (SEQ * INC);
        float* sCf = (float*)sC;
#pragma unroll
        for (int ch = 0; ch < 2; ch++) {
            const int c0 = ch * 12;
            float xr[7][12];
#pragma unroll
            for (int r = 0; r < 7; r++) {
                const int s = sq * 5 - 1 + r;
                if (s >= 0 && s < SEQ) {
                    const float4 v0 = __ldg((const float4*)(xs + s * INC + c0));
                    const float4 v1 = __ldg((const float4*)(xs + s * INC + c0 + 4));
                    const float4 v2 = __ldg((const float4*)(xs + s * INC + c0 + 8));
                    xr[r][0]=v0.x; xr[r][1]=v0.y; xr[r][2]=v0.z; xr[r][3]=v0.w;
                    xr[r][4]=v1.x; xr[r][5]=v1.y; xr[r][6]=v1.z; xr[r][7]=v1.w;
                    xr[r][8]=v2.x; xr[r][9]=v2.y; xr[r][10]=v2.z; xr[r][11]=v2.w;
                } else {
#pragma unroll
                    for (int cc = 0; cc < 12; cc++) xr[r][cc] = 0.0f;
                }
            }
            for (int k = 0; k < NK; k++) {
                float acc[5];
                if (ch == 0) {
                    const float bk = __ldg(&conv_b[k]);
#pragma unroll
                    for (int i = 0; i < 5; i++) acc[i] = bk;
                } else {
#pragma unroll
                    for (int i = 0; i < 5; i++)
                        acc[i] = sCf[sp * SCST + k * SEQ + sq * 5 + i];
                }
#pragma unroll
                for (int cc = 0; cc < 12; cc++) {
                    const float w0 = scw[k * 72 + (c0 + cc) * 3 + 0];
                    const float w1 = scw[k * 72 + (c0 + cc) * 3 + 1];
                    const float w2 = scw[k * 72 + (c0 + cc) * 3 + 2];
#pragma unroll
                    for (int i = 0; i < 5; i++) {
                        acc[i] = fmaf(w0, xr[i][cc],     acc[i]);
                        acc[i] = fmaf(w1, xr[i + 1][cc], acc[i]);
                        acc[i] = fmaf(w2, xr[i + 2][cc], acc[i]);
                    }
                }
#pragma unroll
                for (int i = 0; i < 5; i++)
                    sCf[sp * SCST + k * SEQ + sq * 5 + i] = acc[i];
            }
        }
        // SiLU + tf32 conversion in place (conv writes are thread-private)
        const float* rowf = sCf + sp * SCST;
        unsigned* rowu = sC + sp * SCST;
        for (int e = sq; e < FLAT; e += 8) {
            const float v  = rowf[e];
            const float sg = __fdividef(1.0f, 1.0f + __expf(-v));
            rowu[e] = f2tf(v * sg);
        }
    }

    // ---- enc1 via tf32 mma: C[32 samp][128 out], K=1440 streamed ----
    const int w    = tid >> 5;
    const int lane = tid & 31;
    const int g    = lane >> 2;
    const int tig  = lane & 3;
    const int mh   = w & 1;                  // sample tile (16)
    const int nq   = w >> 1;                 // out tile (32)
    const int srow = mh * 16 + g;
    const int nbase = nq * 32;

    float c[4][4];
#pragma unroll
    for (int nt = 0; nt < 4; nt++) {
        const int n0 = nbase + nt * 8 + 2 * tig;
        c[nt][0] = __ldg(&enc1_b[n0]);
        c[nt][1] = __ldg(&enc1_b[n0 + 1]);
        c[nt][2] = c[nt][0];
        c[nt][3] = c[nt][1];
    }

    for (int kc = 0; kc < FLAT; kc += 32) {
        __syncthreads();
        for (int t2 = tid; t2 < 128 * 32; t2 += 256) {
            const int oc = t2 >> 5, kk = t2 & 31;
            sW[oc * SWST + kk] = f2tf(__ldg(&enc1_w[(size_t)oc * FLAT + kc + kk]));
        }
        __syncthreads();
#pragma unroll
        for (int kt = 0; kt < 4; kt++) {
            unsigned a[4];
            const unsigned* ar = sC + srow * SCST + kc + kt * 8 + tig;
            a[0] = ar[0];
            a[1] = ar[8 * SCST];
            a[2] = ar[4];
            a[3] = ar[8 * SCST + 4];
#pragma unroll
            for (int nt = 0; nt < 4; nt++) {
                const unsigned* br = sW + (nbase + nt * 8 + g) * SWST + kt * 8 + tig;
                mma_tf32(c[nt], a, br[0], br[4]);
            }
        }
    }
    __syncthreads();

    // ReLU -> sH1 [sample][out]
#pragma unroll
    for (int nt = 0; nt < 4; nt++) {
        const int n0 = nbase + nt * 8 + 2 * tig;
        sH1[srow * SH1ST + n0]           = fmaxf(c[nt][0], 0.0f);
        sH1[srow * SH1ST + n0 + 1]       = fmaxf(c[nt][1], 0.0f);
        sH1[(srow + 8) * SH1ST + n0]     = fmaxf(c[nt][2], 0.0f);
        sH1[(srow + 8) * SH1ST + n0 + 1] = fmaxf(c[nt][3], 0.0f);
    }
    __syncthreads();

    // ---- enc2: [128 -> 64] -> g_theta0 transposed [dim][sample] ----
    for (int t = tid; t < ENC_SPB * HID; t += 256) {
        const int oc = t >> 5;                // consecutive lanes -> same oc
        const int sp = t & 31;
        float acc = __ldg(&enc2_b[oc]);
        const float* wr = enc2_w + oc * 128;
        const float* hv = sH1 + sp * SH1ST;
#pragma unroll
        for (int i = 0; i < 128; i += 4) {
            const float4 wv = __ldg((const float4*)(wr + i));
            const float4 h4 = *(const float4*)(hv + i);
            acc = fmaf(wv.x, h4.x, fmaf(wv.y, h4.y, fmaf(wv.z, h4.z, fmaf(wv.w, h4.w, acc))));
        }
        g_theta0[(size_t)oc * B + blk * ENC_SPB + sp] = acc;
    }
}

// ================================ ODE ======================================
// 32 samples/CTA, 256 threads = 8 warps; mma m16n8k8 tf32, W in A-frags.
#define ODE_SPB 32
#define ST 40

// c[nt] = bias + W * in
__device__ __forceinline__ void gemm16x16(
    const unsigned (&A)[8][4], const unsigned* __restrict__ sIn,
    float blo, float bhi, int nbase, int g, int tig, float (&c)[2][4])
{
#pragma unroll
    for (int nt = 0; nt < 2; nt++) {
        c[nt][0] = blo; c[nt][1] = blo; c[nt][2] = bhi; c[nt][3] = bhi;
    }
#pragma unroll
    for (int kt = 0; kt < 8; kt++) {
        const int a0 = (kt * 8 + tig) * ST + nbase + g;
        const int a1 = a0 + 4 * ST;
#pragma unroll
        for (int nt = 0; nt < 2; nt++)
            mma_tf32(c[nt], A[kt], sIn[a0 + nt * 8], sIn[a1 + nt * 8]);
    }
}

__device__ __forceinline__ void store_frag_tf32(
    unsigned* __restrict__ dst, const float (&c)[2][4],
    int m0, int nbase, int tig)
{
#pragma unroll
    for (int nt = 0; nt < 2; nt++) {
        const int n0 = nbase + nt * 8 + 2 * tig;
        uint2 lo; lo.x = f2tf(c[nt][0]); lo.y = f2tf(c[nt][1]);
        uint2 hi; hi.x = f2tf(c[nt][2]); hi.y = f2tf(c[nt][3]);
        *(uint2*)(dst + m0 * ST + n0)       = lo;
        *(uint2*)(dst + (m0 + 8) * ST + n0) = hi;
    }
}

// full f: sY -> k frags.  ONE internal barrier; caller barriers before reuse.
__device__ __forceinline__ void eval_f(
    const unsigned (&A1)[8][4], const unsigned (&A2)[8][4],
    float b1lo, float b1hi, float b2lo, float b2hi,
    const unsigned* __restrict__ sY, unsigned* __restrict__ sH,
    int m0, int nbase, int g, int tig, float (&k)[2][4])
{
    float h[2][4];
    gemm16x16(A1, sY, b1lo, b1hi, nbase, g, tig, h);
#pragma unroll
    for (int nt = 0; nt < 2; nt++)
#pragma unroll
        for (int e = 0; e < 4; e++) h[nt][e] = tanhap(h[nt][e]);
    store_frag_tf32(sH, h, m0, nbase, tig);
    __syncthreads();     // all gemm1 sY reads done; sH complete
    gemm16x16(A2, sH, b2lo, b2hi, nbase, g, tig, k);
}

__global__ void __launch_bounds__(256, 2) ode_kernel(
    const float* __restrict__ t_span,
    const float* __restrict__ w1g, const float* __restrict__ b1g,
    const float* __restrict__ w2g, const float* __restrict__ b2g,
    const float* __restrict__ r1w, const float* __restrict__ r1b,
    const float* __restrict__ r2w, const float* __restrict__ r2b,
    float* __restrict__ out, int B)
{
    __shared__ unsigned sY[HID * ST];
    __shared__ unsigned sH[HID * ST];

    const int tid  = threadIdx.x;
    const int w    = tid >> 5;
    const int lane = tid & 31;
    const int g    = lane >> 2;
    const int tig  = lane & 3;
    const int mw   = w & 3;
    const int nh   = w >> 2;
    const int m0   = mw * 16 + g;
    const int nbase = nh * 16;

    unsigned A1[8][4], A2[8][4];
#pragma unroll
    for (int kt = 0; kt < 8; kt++) {
        const int k0 = kt * 8 + tig;
        A1[kt][0] = f2tf(__ldg(&w1g[(m0)     * HID + k0]));
        A1[kt][1] = f2tf(__ldg(&w1g[(m0 + 8) * HID + k0]));
        A1[kt][2] = f2tf(__ldg(&w1g[(m0)     * HID + k0 + 4]));
        A1[kt][3] = f2tf(__ldg(&w1g[(m0 + 8) * HID + k0 + 4]));
        A2[kt][0] = f2tf(__ldg(&w2g[(m0)     * HID + k0]));
        A2[kt][1] = f2tf(__ldg(&w2g[(m0 + 8) * HID + k0]));
        A2[kt][2] = f2tf(__ldg(&w2g[(m0)     * HID + k0 + 4]));
        A2[kt][3] = f2tf(__ldg(&w2g[(m0 + 8) * HID + k0 + 4]));
    }
    const float b1lo = __ldg(&b1g[m0]), b1hi = __ldg(&b1g[m0 + 8]);
    const float b2lo = __ldg(&b2g[m0]), b2hi = __ldg(&b2g[m0 + 8]);

    const float dt = (__ldg(&t_span[1]) - __ldg(&t_span[0])) * (1.0f / STEPS);

    const long long gbase = (long long)blockIdx.x * ODE_SPB;
    float y[2][4];
#pragma unroll
    for (int nt = 0; nt < 2; nt++) {
        const long long n0 = gbase + nbase + nt * 8 + 2 * tig;
        y[nt][0] = __ldg(&g_theta0[(size_t)m0 * B + n0]);
        y[nt][1] = __ldg(&g_theta0[(size_t)m0 * B + n0 + 1]);
        y[nt][2] = __ldg(&g_theta0[(size_t)(m0 + 8) * B + n0]);
        y[nt][3] = __ldg(&g_theta0[(size_t)(m0 + 8) * B + n0 + 1]);
    }
    store_frag_tf32(sY, y, m0, nbase, tig);
    __syncthreads();

    float k1[2][4], k2[2][4], k3[2][4], k4[2][4], k5[2][4], k6[2][4], nv[2][4];

#define ELEM_LOOP(expr)                                                        \
    _Pragma("unroll") for (int nt = 0; nt < 2; nt++)                           \
    _Pragma("unroll") for (int e = 0; e < 4; e++) { expr; }

    for (int step = 0; step < STEPS; step++) {
        eval_f(A1, A2, b1lo, b1hi, b2lo, b2hi, sY, sH, m0, nbase, g, tig, k1);
        {
            const float c1 = dt * 0.2f;
            ELEM_LOOP(nv[nt][e] = fmaf(c1, k1[nt][e], y[nt][e]));
            store_frag_tf32(sY, nv, m0, nbase, tig);
        }
        __syncthreads();
        eval_f(A1, A2, b1lo, b1hi, b2lo, b2hi, sY, sH, m0, nbase, g, tig, k2);
        {
            const float c1 = dt * (3.0f / 40.0f), c2 = dt * (9.0f / 40.0f);
            ELEM_LOOP(nv[nt][e] = fmaf(c1, k1[nt][e], fmaf(c2, k2[nt][e], y[nt][e])));
            store_frag_tf32(sY, nv, m0, nbase, tig);
        }
        __syncthreads();
        eval_f(A1, A2, b1lo, b1hi, b2lo, b2hi, sY, sH, m0, nbase, g, tig, k3);
        {
            const float c1 = dt * (44.0f / 45.0f), c2 = dt * (-56.0f / 15.0f),
                        c3 = dt * (32.0f / 9.0f);
            ELEM_LOOP(nv[nt][e] = fmaf(c1, k1[nt][e], fmaf(c2, k2[nt][e],
                                  fmaf(c3, k3[nt][e], y[nt][e]))));
            store_frag_tf32(sY, nv, m0, nbase, tig);
        }
        __syncthreads();
        eval_f(A1, A2, b1lo, b1hi, b2lo, b2hi, sY, sH, m0, nbase, g, tig, k4);
        {
            const float c1 = dt * (19372.0f / 6561.0f), c2 = dt * (-25360.0f / 2187.0f),
                        c3 = dt * (64448.0f / 6561.0f), c4 = dt * (-212.0f / 729.0f);
            ELEM_LOOP(nv[nt][e] = fmaf(c1, k1[nt][e], fmaf(c2, k2[nt][e],
                                  fmaf(c3, k3[nt][e], fmaf(c4, k4[nt][e], y[nt][e])))));
            store_frag_tf32(sY, nv, m0, nbase, tig);
        }
        __syncthreads();
        eval_f(A1, A2, b1lo, b1hi, b2lo, b2hi, sY, sH, m0, nbase, g, tig, k5);
        {
            const float c1 = dt * (9017.0f / 3168.0f), c2 = dt * (-355.0f / 33.0f),
                        c3 = dt * (46732.0f / 5247.0f), c4 = dt * (49.0f / 176.0f),
                        c5 = dt * (-5103.0f / 18656.0f);
            ELEM_LOOP(nv[nt][e] = fmaf(c1, k1[nt][e], fmaf(c2, k2[nt][e],
                                  fmaf(c3, k3[nt][e], fmaf(c4, k4[nt][e],
                                  fmaf(c5, k5[nt][e], y[nt][e]))))));
            store_frag_tf32(sY, nv, m0, nbase, tig);
        }
        __syncthreads();
        eval_f(A1, A2, b1lo, b1hi, b2lo, b2hi, sY, sH, m0, nbase, g, tig, k6);
        {
            const float c1 = dt * (35.0f / 384.0f),  c3 = dt * (500.0f / 1113.0f),
                        c4 = dt * (125.0f / 192.0f), c5 = dt * (-2187.0f / 6784.0f),
                        c6 = dt * (11.0f / 84.0f);
            ELEM_LOOP(y[nt][e] = fmaf(c1, k1[nt][e], fmaf(c3, k3[nt][e],
                                 fmaf(c4, k4[nt][e], fmaf(c5, k5[nt][e],
                                 fmaf(c6, k6[nt][e], y[nt][e]))))));
            store_frag_tf32(sY, y, m0, nbase, tig);
        }
        __syncthreads();
    }

    // overwrite sY with full-precision y for the regressor
#pragma unroll
    for (int nt = 0; nt < 2; nt++) {
        const int n0 = nbase + nt * 8 + 2 * tig;
        float* sYf = (float*)sY;
        sYf[m0 * ST + n0]           = y[nt][0];
        sYf[m0 * ST + n0 + 1]       = y[nt][1];
        sYf[(m0 + 8) * ST + n0]     = y[nt][2];
        sYf[(m0 + 8) * ST + n0 + 1] = y[nt][3];
    }
    __syncthreads();

    // ---- regressor: threads 0..127, 4 per sample ----
    if (tid < 128) {
        const float* sYf = (const float*)sY;
        const int s  = tid >> 2;
        const int mg = (tid & 3) * 8;
        float accm[8];
#pragma unroll
        for (int m = 0; m < 8; m++) accm[m] = __ldg(&r1b[mg + m]);
        for (int i = 0; i < HID; i++) {
            const float yy = sYf[i * ST + s];
#pragma unroll
            for (int m = 0; m < 8; m++)
                accm[m] = fmaf(__ldg(&r1w[(mg + m) * HID + i]), yy, accm[m]);
        }
        float part = 0.0f;
#pragma unroll
        for (int m = 0; m < 8; m++)
            part = fmaf(__ldg(&r2w[mg + m]), fmaxf(accm[m], 0.0f), part);
        part += __shfl_xor_sync(0xffffffffu, part, 1);
        part += __shfl_xor_sync(0xffffffffu, part, 2);
        if ((tid & 3) == 0)
            out[(long long)blockIdx.x * ODE_SPB + s] = part + __ldg(&r2b[0]);
    }
}

// ============================== launch ======================================
extern "C" void kernel_launch(void* const* d_in, const int* in_sizes, int n_in,
                              void* d_out, int out_size)
{
    const float* x      = (const float*)d_in[0];
    const float* t_span = (const float*)d_in[1];
    const float* conv_w = (const float*)d_in[2];
    const float* conv_b = (const float*)d_in[3];
    const float* enc1_w = (const float*)d_in[4];
    const float* enc1_b = (const float*)d_in[5];
    const float* enc2_w = (const float*)d_in[6];
    const float* enc2_b = (const float*)d_in[7];
    const float* ode1_w = (const float*)d_in[8];
    const float* ode1_b = (const float*)d_in[9];
    const float* ode2_w = (const float*)d_in[10];
    const float* ode2_b = (const float*)d_in[11];
    const float* reg1_w = (const float*)d_in[12];
    const float* reg1_b = (const float*)d_in[13];
    const float* reg2_w = (const float*)d_in[14];
    const float* reg2_b = (const float*)d_in[15];
    float* out = (float*)d_out;

    const int B = in_sizes[0] / (SEQ * INC);

    cudaFuncSetAttribute(enc_kernel, cudaFuncAttributeMaxDynamicSharedMemorySize,
                         ENC_SMEM_BYTES);

    enc_kernel<<<B / ENC_SPB, 256, ENC_SMEM_BYTES>>>(
        x, conv_w, conv_b, enc1_w, enc1_b, enc2_w, enc2_b, B);
    ode_kernel<<<B / ODE_SPB, 256>>>(
        t_span, ode1_w, ode1_b, ode2_w, ode2_b,
        reg1_w, reg1_b, reg2_w, reg2_b, out, B);
}

// round 10
// speedup vs baseline: 7.3286x; 1.1331x over previous
#include <cuda_runtime.h>
#include <cuda_bf16.h>

// ---------------------------------------------------------------------------
// CNN_ODE: conv1d+SiLU -> MLP encoder (tf32 mma, double-buffered) -> 50-step
// fixed dopri5 (64-dim neural ODE, tf32 mma) -> regressor.  B = 65536.
// ---------------------------------------------------------------------------

#define SEQ   40
#define INC   24
#define NK    36
#define FLAT  1440
#define HID   64
#define STEPS 50

// theta0 scratch, TRANSPOSED: [dim][sample], float
__device__ float g_theta0[HID * 65536];   // 16 MB

__device__ __forceinline__ float tanhap(float x) {
    float r; asm("tanh.approx.f32 %0,%1;" : "=f"(r) : "f"(x)); return r;
}
__device__ __forceinline__ unsigned f2tf(float f) {
    unsigned u; asm("cvt.rna.tf32.f32 %0,%1;" : "=r"(u) : "f"(f)); return u;
}
__device__ __forceinline__ void mma_tf32(
    float (&c)[4], const unsigned (&a)[4], unsigned b0, unsigned b1)
{
    asm("mma.sync.aligned.m16n8k8.row.col.f32.tf32.tf32.f32 "
        "{%0,%1,%2,%3},{%4,%5,%6,%7},{%8,%9},{%0,%1,%2,%3};"
        : "+f"(c[0]), "+f"(c[1]), "+f"(c[2]), "+f"(c[3])
        : "r"(a[0]), "r"(a[1]), "r"(a[2]), "r"(a[3]), "r"(b0), "r"(b1));
}

// ============================== Encoder ====================================
// 32 samples/CTA, 256 threads.
//  conv (SIMT, x in regs, two c-halves; SiLU+tf32 folded into 2nd pass)
//  enc1: tf32 mma, M=32 samp x N=128 out x K=1440, DOUBLE-BUFFERED weights
//  enc2: SIMT [128->64] -> g_theta0 transposed
#define ENC_SPB 32
#define SCST    1444                   // sC row stride (uints); %32==4, %4==0
#define SWST    36                     // weight chunk row stride; %32==4
#define SH1ST   132                    // sH1 row stride; %32==4
#define NCHUNK  (FLAT / 32)            // 45
// smem: sC [32][1444] + sW[2][128][36];  sH1 aliases sC (dead after k-loop)
#define ENC_SMEM_BYTES ((ENC_SPB*SCST + 2*128*SWST) * 4)

__global__ void __launch_bounds__(256) enc_kernel(
    const float* __restrict__ x,
    const float* __restrict__ conv_w, const float* __restrict__ conv_b,
    const float* __restrict__ enc1_w, const float* __restrict__ enc1_b,
    const float* __restrict__ enc2_w, const float* __restrict__ enc2_b,
    int B)
{
    extern __shared__ unsigned smu[];
    unsigned* sC  = smu;                          // [32][SCST] tf32 after conv
    unsigned* sW0 = sC + ENC_SPB * SCST;          // [128][SWST] buffer 0
    unsigned* sW1 = sW0 + 128 * SWST;             // [128][SWST] buffer 1
    float*    sH1 = (float*)sC;                   // [32][SH1ST] (aliases sC)

    const int tid = threadIdx.x;
    const long long blk = blockIdx.x;

    // ---- stage conv weights into sW area (free until enc1 k-loop) ----
    float* scw = (float*)sW0;                     // 2592 floats
    for (int i = tid; i < NK * 72; i += 256) scw[i] = conv_w[i];
    __syncthreads();

    // ---- conv1d (pad=1): thread = (sample, 5-wide s-range), two c-halves ----
    {
        const int sp = tid >> 3;                  // 0..31
        const int sq = tid & 7;                   // s-range [5sq, 5sq+5)
        const float* xs = x + (blk * ENC_SPB + sp) * (SEQ * INC);
        float* sCf = (float*)sC;
#pragma unroll
        for (int ch = 0; ch < 2; ch++) {
            const int c0 = ch * 12;
            float xr[7][12];
#pragma unroll
            for (int r = 0; r < 7; r++) {
                const int s = sq * 5 - 1 + r;
                if (s >= 0 && s < SEQ) {
                    const float4 v0 = __ldg((const float4*)(xs + s * INC + c0));
                    const float4 v1 = __ldg((const float4*)(xs + s * INC + c0 + 4));
                    const float4 v2 = __ldg((const float4*)(xs + s * INC + c0 + 8));
                    xr[r][0]=v0.x; xr[r][1]=v0.y; xr[r][2]=v0.z; xr[r][3]=v0.w;
                    xr[r][4]=v1.x; xr[r][5]=v1.y; xr[r][6]=v1.z; xr[r][7]=v1.w;
                    xr[r][8]=v2.x; xr[r][9]=v2.y; xr[r][10]=v2.z; xr[r][11]=v2.w;
                } else {
#pragma unroll
                    for (int cc = 0; cc < 12; cc++) xr[r][cc] = 0.0f;
                }
            }
            for (int k = 0; k < NK; k++) {
                float acc[5];
                if (ch == 0) {
                    const float bk = __ldg(&conv_b[k]);
#pragma unroll
                    for (int i = 0; i < 5; i++) acc[i] = bk;
                } else {
#pragma unroll
                    for (int i = 0; i < 5; i++)
                        acc[i] = sCf[sp * SCST + k * SEQ + sq * 5 + i];
                }
#pragma unroll
                for (int cc = 0; cc < 12; cc++) {
                    const float w0 = scw[k * 72 + (c0 + cc) * 3 + 0];
                    const float w1 = scw[k * 72 + (c0 + cc) * 3 + 1];
                    const float w2 = scw[k * 72 + (c0 + cc) * 3 + 2];
#pragma unroll
                    for (int i = 0; i < 5; i++) {
                        acc[i] = fmaf(w0, xr[i][cc],     acc[i]);
                        acc[i] = fmaf(w1, xr[i + 1][cc], acc[i]);
                        acc[i] = fmaf(w2, xr[i + 2][cc], acc[i]);
                    }
                }
                if (ch == 0) {
#pragma unroll
                    for (int i = 0; i < 5; i++)
                        sCf[sp * SCST + k * SEQ + sq * 5 + i] = acc[i];
                } else {
                    // finish: SiLU + tf32, in place (thread-private elements)
#pragma unroll
                    for (int i = 0; i < 5; i++) {
                        const float v  = acc[i];
                        const float sg = fmaf(0.5f, tanhap(0.5f * v), 0.5f);
                        sC[sp * SCST + k * SEQ + sq * 5 + i] = f2tf(v * sg);
                    }
                }
            }
        }
    }
    __syncthreads();   // conv done; scw (sW0 area) free for weight buffers

    // ---- enc1 via tf32 mma: C[32 samp][128 out], K streamed, double-buffer --
    const int w    = tid >> 5;
    const int lane = tid & 31;
    const int g    = lane >> 2;
    const int tig  = lane & 3;
    const int mh   = w & 1;                  // sample tile (16)
    const int nq   = w >> 1;                 // out tile (32)
    const int srow = mh * 16 + g;
    const int nbase = nq * 32;

    float c[4][4];
#pragma unroll
    for (int nt = 0; nt < 4; nt++) {
        const int n0 = nbase + nt * 8 + 2 * tig;
        c[nt][0] = __ldg(&enc1_b[n0]);
        c[nt][1] = __ldg(&enc1_b[n0 + 1]);
        c[nt][2] = c[nt][0];
        c[nt][3] = c[nt][1];
    }

    // prefetch mapping: 1024 float4 per chunk, 4 per thread
    // f -> row oc = f>>3, quad (f&7): gmem enc1_w[oc*FLAT + kc + (f&7)*4]
    float4 pre[4];
    {
        const int kc = 0;
#pragma unroll
        for (int j = 0; j < 4; j++) {
            const int f  = tid + j * 256;
            const int oc = f >> 3, qd = f & 7;
            pre[j] = __ldg((const float4*)(enc1_w + (size_t)oc * FLAT + kc + qd * 4));
        }
    }

    for (int kci = 0; kci < NCHUNK; kci++) {
        unsigned* buf = (kci & 1) ? sW1 : sW0;
        // store prefetched chunk (tf32)
#pragma unroll
        for (int j = 0; j < 4; j++) {
            const int f  = tid + j * 256;
            const int oc = f >> 3, qd = f & 7;
            uint4 u;
            u.x = f2tf(pre[j].x); u.y = f2tf(pre[j].y);
            u.z = f2tf(pre[j].z); u.w = f2tf(pre[j].w);
            *(uint4*)(buf + oc * SWST + qd * 4) = u;
        }
        // prefetch next chunk
        if (kci + 1 < NCHUNK) {
            const int kc = (kci + 1) * 32;
#pragma unroll
            for (int j = 0; j < 4; j++) {
                const int f  = tid + j * 256;
                const int oc = f >> 3, qd = f & 7;
                pre[j] = __ldg((const float4*)(enc1_w + (size_t)oc * FLAT + kc + qd * 4));
            }
        }
        __syncthreads();
        const int kc = kci * 32;
#pragma unroll
        for (int kt = 0; kt < 4; kt++) {
            unsigned a[4];
            const unsigned* ar = sC + srow * SCST + kc + kt * 8 + tig;
            a[0] = ar[0];
            a[1] = ar[8 * SCST];
            a[2] = ar[4];
            a[3] = ar[8 * SCST + 4];
#pragma unroll
            for (int nt = 0; nt < 4; nt++) {
                const unsigned* br = buf + (nbase + nt * 8 + g) * SWST + kt * 8 + tig;
                mma_tf32(c[nt], a, br[0], br[4]);
            }
        }
    }
    __syncthreads();   // all mma reads of sC done -> sH1 may overwrite it

    // ReLU -> sH1 [sample][out]
#pragma unroll
    for (int nt = 0; nt < 4; nt++) {
        const int n0 = nbase + nt * 8 + 2 * tig;
        sH1[srow * SH1ST + n0]           = fmaxf(c[nt][0], 0.0f);
        sH1[srow * SH1ST + n0 + 1]       = fmaxf(c[nt][1], 0.0f);
        sH1[(srow + 8) * SH1ST + n0]     = fmaxf(c[nt][2], 0.0f);
        sH1[(srow + 8) * SH1ST + n0 + 1] = fmaxf(c[nt][3], 0.0f);
    }
    __syncthreads();

    // ---- enc2: [128 -> 64] -> g_theta0 transposed [dim][sample] ----
    for (int t = tid; t < ENC_SPB * HID; t += 256) {
        const int oc = t >> 5;                // consecutive lanes -> same oc
        const int sp = t & 31;
        float acc = __ldg(&enc2_b[oc]);
        const float* wr = enc2_w + oc * 128;
        const float* hv = sH1 + sp * SH1ST;
#pragma unroll
        for (int i = 0; i < 128; i += 4) {
            const float4 wv = __ldg((const float4*)(wr + i));
            const float4 h4 = *(const float4*)(hv + i);
            acc = fmaf(wv.x, h4.x, fmaf(wv.y, h4.y, fmaf(wv.z, h4.z, fmaf(wv.w, h4.w, acc))));
        }
        g_theta0[(size_t)oc * B + blk * ENC_SPB + sp] = acc;
    }
}

// ================================ ODE ======================================
// 32 samples/CTA, 256 threads = 8 warps; mma m16n8k8 tf32, W in A-frags.
#define ODE_SPB 32
#define ST 40

__device__ __forceinline__ void gemm16x16(
    const unsigned (&A)[8][4], const unsigned* __restrict__ sIn,
    float blo, float bhi, int nbase, int g, int tig, float (&c)[2][4])
{
#pragma unroll
    for (int nt = 0; nt < 2; nt++) {
        c[nt][0] = blo; c[nt][1] = blo; c[nt][2] = bhi; c[nt][3] = bhi;
    }
#pragma unroll
    for (int kt = 0; kt < 8; kt++) {
        const int a0 = (kt * 8 + tig) * ST + nbase + g;
        const int a1 = a0 + 4 * ST;
#pragma unroll
        for (int nt = 0; nt < 2; nt++)
            mma_tf32(c[nt], A[kt], sIn[a0 + nt * 8], sIn[a1 + nt * 8]);
    }
}

__device__ __forceinline__ void store_frag_tf32(
    unsigned* __restrict__ dst, const float (&c)[2][4],
    int m0, int nbase, int tig)
{
#pragma unroll
    for (int nt = 0; nt < 2; nt++) {
        const int n0 = nbase + nt * 8 + 2 * tig;
        uint2 lo; lo.x = f2tf(c[nt][0]); lo.y = f2tf(c[nt][1]);
        uint2 hi; hi.x = f2tf(c[nt][2]); hi.y = f2tf(c[nt][3]);
        *(uint2*)(dst + m0 * ST + n0)       = lo;
        *(uint2*)(dst + (m0 + 8) * ST + n0) = hi;
    }
}

__device__ __forceinline__ void eval_f(
    const unsigned (&A1)[8][4], const unsigned (&A2)[8][4],
    float b1lo, float b1hi, float b2lo, float b2hi,
    const unsigned* __restrict__ sY, unsigned* __restrict__ sH,
    int m0, int nbase, int g, int tig, float (&k)[2][4])
{
    float h[2][4];
    gemm16x16(A1, sY, b1lo, b1hi, nbase, g, tig, h);
#pragma unroll
    for (int nt = 0; nt < 2; nt++)
#pragma unroll
        for (int e = 0; e < 4; e++) h[nt][e] = tanhap(h[nt][e]);
    store_frag_tf32(sH, h, m0, nbase, tig);
    __syncthreads();     // all gemm1 sY reads done; sH complete
    gemm16x16(A2, sH, b2lo, b2hi, nbase, g, tig, k);
}

__global__ void __launch_bounds__(256, 2) ode_kernel(
    const float* __restrict__ t_span,
    const float* __restrict__ w1g, const float* __restrict__ b1g,
    const float* __restrict__ w2g, const float* __restrict__ b2g,
    const float* __restrict__ r1w, const float* __restrict__ r1b,
    const float* __restrict__ r2w, const float* __restrict__ r2b,
    float* __restrict__ out, int B)
{
    __shared__ unsigned sY[HID * ST];
    __shared__ unsigned sH[HID * ST];

    const int tid  = threadIdx.x;
    const int w    = tid >> 5;
    const int lane = tid & 31;
    const int g    = lane >> 2;
    const int tig  = lane & 3;
    const int mw   = w & 3;
    const int nh   = w >> 2;
    const int m0   = mw * 16 + g;
    const int nbase = nh * 16;

    unsigned A1[8][4], A2[8][4];
#pragma unroll
    for (int kt = 0; kt < 8; kt++) {
        const int k0 = kt * 8 + tig;
        A1[kt][0] = f2tf(__ldg(&w1g[(m0)     * HID + k0]));
        A1[kt][1] = f2tf(__ldg(&w1g[(m0 + 8) * HID + k0]));
        A1[kt][2] = f2tf(__ldg(&w1g[(m0)     * HID + k0 + 4]));
        A1[kt][3] = f2tf(__ldg(&w1g[(m0 + 8) * HID + k0 + 4]));
        A2[kt][0] = f2tf(__ldg(&w2g[(m0)     * HID + k0]));
        A2[kt][1] = f2tf(__ldg(&w2g[(m0 + 8) * HID + k0]));
        A2[kt][2] = f2tf(__ldg(&w2g[(m0)     * HID + k0 + 4]));
        A2[kt][3] = f2tf(__ldg(&w2g[(m0 + 8) * HID + k0 + 4]));
    }
    const float b1lo = __ldg(&b1g[m0]), b1hi = __ldg(&b1g[m0 + 8]);
    const float b2lo = __ldg(&b2g[m0]), b2hi = __ldg(&b2g[m0 + 8]);

    const float dt = (__ldg(&t_span[1]) - __ldg(&t_span[0])) * (1.0f / STEPS);

    const long long gbase = (long long)blockIdx.x * ODE_SPB;
    float y[2][4];
#pragma unroll
    for (int nt = 0; nt < 2; nt++) {
        const long long n0 = gbase + nbase + nt * 8 + 2 * tig;
        y[nt][0] = __ldg(&g_theta0[(size_t)m0 * B + n0]);
        y[nt][1] = __ldg(&g_theta0[(size_t)m0 * B + n0 + 1]);
        y[nt][2] = __ldg(&g_theta0[(size_t)(m0 + 8) * B + n0]);
        y[nt][3] = __ldg(&g_theta0[(size_t)(m0 + 8) * B + n0 + 1]);
    }
    store_frag_tf32(sY, y, m0, nbase, tig);
    __syncthreads();

    float k1[2][4], k2[2][4], k3[2][4], k4[2][4], k5[2][4], k6[2][4], nv[2][4];

#define ELEM_LOOP(expr)                                                        \
    _Pragma("unroll") for (int nt = 0; nt < 2; nt++)                           \
    _Pragma("unroll") for (int e = 0; e < 4; e++) { expr; }

    for (int step = 0; step < STEPS; step++) {
        eval_f(A1, A2, b1lo, b1hi, b2lo, b2hi, sY, sH, m0, nbase, g, tig, k1);
        {
            const float c1 = dt * 0.2f;
            ELEM_LOOP(nv[nt][e] = fmaf(c1, k1[nt][e], y[nt][e]));
            store_frag_tf32(sY, nv, m0, nbase, tig);
        }
        __syncthreads();
        eval_f(A1, A2, b1lo, b1hi, b2lo, b2hi, sY, sH, m0, nbase, g, tig, k2);
        {
            const float c1 = dt * (3.0f / 40.0f), c2 = dt * (9.0f / 40.0f);
            ELEM_LOOP(nv[nt][e] = fmaf(c1, k1[nt][e], fmaf(c2, k2[nt][e], y[nt][e])));
            store_frag_tf32(sY, nv, m0, nbase, tig);
        }
        __syncthreads();
        eval_f(A1, A2, b1lo, b1hi, b2lo, b2hi, sY, sH, m0, nbase, g, tig, k3);
        {
            const float c1 = dt * (44.0f / 45.0f), c2 = dt * (-56.0f / 15.0f),
                        c3 = dt * (32.0f / 9.0f);
            ELEM_LOOP(nv[nt][e] = fmaf(c1, k1[nt][e], fmaf(c2, k2[nt][e],
                                  fmaf(c3, k3[nt][e], y[nt][e]))));
            store_frag_tf32(sY, nv, m0, nbase, tig);
        }
        __syncthreads();
        eval_f(A1, A2, b1lo, b1hi, b2lo, b2hi, sY, sH, m0, nbase, g, tig, k4);
        {
            const float c1 = dt * (19372.0f / 6561.0f), c2 = dt * (-25360.0f / 2187.0f),
                        c3 = dt * (64448.0f / 6561.0f), c4 = dt * (-212.0f / 729.0f);
            ELEM_LOOP(nv[nt][e] = fmaf(c1, k1[nt][e], fmaf(c2, k2[nt][e],
                                  fmaf(c3, k3[nt][e], fmaf(c4, k4[nt][e], y[nt][e])))));
            store_frag_tf32(sY, nv, m0, nbase, tig);
        }
        __syncthreads();
        eval_f(A1, A2, b1lo, b1hi, b2lo, b2hi, sY, sH, m0, nbase, g, tig, k5);
        {
            const float c1 = dt * (9017.0f / 3168.0f), c2 = dt * (-355.0f / 33.0f),
                        c3 = dt * (46732.0f / 5247.0f), c4 = dt * (49.0f / 176.0f),
                        c5 = dt * (-5103.0f / 18656.0f);
            ELEM_LOOP(nv[nt][e] = fmaf(c1, k1[nt][e], fmaf(c2, k2[nt][e],
                                  fmaf(c3, k3[nt][e], fmaf(c4, k4[nt][e],
                                  fmaf(c5, k5[nt][e], y[nt][e]))))));
            store_frag_tf32(sY, nv, m0, nbase, tig);
        }
        __syncthreads();
        eval_f(A1, A2, b1lo, b1hi, b2lo, b2hi, sY, sH, m0, nbase, g, tig, k6);
        {
            const float c1 = dt * (35.0f / 384.0f),  c3 = dt * (500.0f / 1113.0f),
                        c4 = dt * (125.0f / 192.0f), c5 = dt * (-2187.0f / 6784.0f),
                        c6 = dt * (11.0f / 84.0f);
            ELEM_LOOP(y[nt][e] = fmaf(c1, k1[nt][e], fmaf(c3, k3[nt][e],
                                 fmaf(c4, k4[nt][e], fmaf(c5, k5[nt][e],
                                 fmaf(c6, k6[nt][e], y[nt][e]))))));
            store_frag_tf32(sY, y, m0, nbase, tig);
        }
        __syncthreads();
    }

    // overwrite sY with full-precision y for the regressor
#pragma unroll
    for (int nt = 0; nt < 2; nt++) {
        const int n0 = nbase + nt * 8 + 2 * tig;
        float* sYf = (float*)sY;
        sYf[m0 * ST + n0]           = y[nt][0];
        sYf[m0 * ST + n0 + 1]       = y[nt][1];
        sYf[(m0 + 8) * ST + n0]     = y[nt][2];
        sYf[(m0 + 8) * ST + n0 + 1] = y[nt][3];
    }
    __syncthreads();

    // ---- regressor: threads 0..127, 4 per sample ----
    if (tid < 128) {
        const float* sYf = (const float*)sY;
        const int s  = tid >> 2;
        const int mg = (tid & 3) * 8;
        float accm[8];
#pragma unroll
        for (int m = 0; m < 8; m++) accm[m] = __ldg(&r1b[mg + m]);
        for (int i = 0; i < HID; i++) {
            const float yy = sYf[i * ST + s];
#pragma unroll
            for (int m = 0; m < 8; m++)
                accm[m] = fmaf(__ldg(&r1w[(mg + m) * HID + i]), yy, accm[m]);
        }
        float part = 0.0f;
#pragma unroll
        for (int m = 0; m < 8; m++)
            part = fmaf(__ldg(&r2w[mg + m]), fmaxf(accm[m], 0.0f), part);
        part += __shfl_xor_sync(0xffffffffu, part, 1);
        part += __shfl_xor_sync(0xffffffffu, part, 2);
        if ((tid & 3) == 0)
            out[(long long)blockIdx.x * ODE_SPB + s] = part + __ldg(&r2b[0]);
    }
}

// ============================== launch ======================================
extern "C" void kernel_launch(void* const* d_in, const int* in_sizes, int n_in,
                              void* d_out, int out_size)
{
    const float* x      = (const float*)d_in[0];
    const float* t_span = (const float*)d_in[1];
    const float* conv_w = (const float*)d_in[2];
    const float* conv_b = (const float*)d_in[3];
    const float* enc1_w = (const float*)d_in[4];
    const float* enc1_b = (const float*)d_in[5];
    const float* enc2_w = (const float*)d_in[6];
    const float* enc2_b = (const float*)d_in[7];
    const float* ode1_w = (const float*)d_in[8];
    const float* ode1_b = (const float*)d_in[9];
    const float* ode2_w = (const float*)d_in[10];
    const float* ode2_b = (const float*)d_in[11];
    const float* reg1_w = (const float*)d_in[12];
    const float* reg1_b = (const float*)d_in[13];
    const float* reg2_w = (const float*)d_in[14];
    const float* reg2_b = (const float*)d_in[15];
    float* out = (float*)d_out;

    const int B = in_sizes[0] / (SEQ * INC);

    cudaFuncSetAttribute(enc_kernel, cudaFuncAttributeMaxDynamicSharedMemorySize,
                         ENC_SMEM_BYTES);

    enc_kernel<<<B / ENC_SPB, 256, ENC_SMEM_BYTES>>>(
        x, conv_w, conv_b, enc1_w, enc1_b, enc2_w, enc2_b, B);
    ode_kernel<<<B / ODE_SPB, 256>>>(
        t_span, ode1_w, ode1_b, ode2_w, ode2_b,
        reg1_w, reg1_b, reg2_w, reg2_b, out, B);
}

// round 11
// speedup vs baseline: 9.7557x; 1.3312x over previous
#include <cuda_runtime.h>
#include <cuda_bf16.h>
#include <cuda_fp16.h>

// ---------------------------------------------------------------------------
// CNN_ODE: conv1d+SiLU -> MLP encoder (tf32 mma, double-buffered) -> 50-step
// fixed dopri5 (64-dim neural ODE, fp16 m16n8k16 mma) -> regressor.  B=65536.
// ---------------------------------------------------------------------------

#define SEQ   40
#define INC   24
#define NK    36
#define FLAT  1440
#define HID   64
#define STEPS 50

// theta0 scratch, TRANSPOSED: [dim][sample], float
__device__ float g_theta0[HID * 65536];   // 16 MB

__device__ __forceinline__ float tanhap(float x) {
    float r; asm("tanh.approx.f32 %0,%1;" : "=f"(r) : "f"(x)); return r;
}
__device__ __forceinline__ unsigned f2tf(float f) {
    unsigned u; asm("cvt.rna.tf32.f32 %0,%1;" : "=r"(u) : "f"(f)); return u;
}
__device__ __forceinline__ void mma_tf32(
    float (&c)[4], const unsigned (&a)[4], unsigned b0, unsigned b1)
{
    asm("mma.sync.aligned.m16n8k8.row.col.f32.tf32.tf32.f32 "
        "{%0,%1,%2,%3},{%4,%5,%6,%7},{%8,%9},{%0,%1,%2,%3};"
        : "+f"(c[0]), "+f"(c[1]), "+f"(c[2]), "+f"(c[3])
        : "r"(a[0]), "r"(a[1]), "r"(a[2]), "r"(a[3]), "r"(b0), "r"(b1));
}
__device__ __forceinline__ void mma_fp16(
    float (&c)[4], const unsigned (&a)[4], unsigned b0, unsigned b1)
{
    asm("mma.sync.aligned.m16n8k16.row.col.f32.f16.f16.f32 "
        "{%0,%1,%2,%3},{%4,%5,%6,%7},{%8,%9},{%0,%1,%2,%3};"
        : "+f"(c[0]), "+f"(c[1]), "+f"(c[2]), "+f"(c[3])
        : "r"(a[0]), "r"(a[1]), "r"(a[2]), "r"(a[3]), "r"(b0), "r"(b1));
}
__device__ __forceinline__ unsigned pkh2(float a, float b) {
    __half2 h = __floats2half2_rn(a, b);
    return *reinterpret_cast<unsigned*>(&h);
}

// ============================== Encoder ====================================
// 32 samples/CTA, 256 threads.  (unchanged from R10)
#define ENC_SPB 32
#define SCST    1444
#define SWST    36
#define SH1ST   132
#define NCHUNK  (FLAT / 32)            // 45
#define ENC_SMEM_BYTES ((ENC_SPB*SCST + 2*128*SWST) * 4)

__global__ void __launch_bounds__(256) enc_kernel(
    const float* __restrict__ x,
    const float* __restrict__ conv_w, const float* __restrict__ conv_b,
    const float* __restrict__ enc1_w, const float* __restrict__ enc1_b,
    const float* __restrict__ enc2_w, const float* __restrict__ enc2_b,
    int B)
{
    extern __shared__ unsigned smu[];
    unsigned* sC  = smu;                          // [32][SCST] tf32 after conv
    unsigned* sW0 = sC + ENC_SPB * SCST;          // [128][SWST]
    unsigned* sW1 = sW0 + 128 * SWST;             // [128][SWST]
    float*    sH1 = (float*)sC;                   // [32][SH1ST] (aliases sC)

    const int tid = threadIdx.x;
    const long long blk = blockIdx.x;

    float* scw = (float*)sW0;
    for (int i = tid; i < NK * 72; i += 256) scw[i] = conv_w[i];
    __syncthreads();

    // ---- conv1d (pad=1) + fused SiLU/tf32 on second c-half ----
    {
        const int sp = tid >> 3;
        const int sq = tid & 7;
        const float* xs = x + (blk * ENC_SPB + sp) * (SEQ * INC);
        float* sCf = (float*)sC;
#pragma unroll
        for (int ch = 0; ch < 2; ch++) {
            const int c0 = ch * 12;
            float xr[7][12];
#pragma unroll
            for (int r = 0; r < 7; r++) {
                const int s = sq * 5 - 1 + r;
                if (s >= 0 && s < SEQ) {
                    const float4 v0 = __ldg((const float4*)(xs + s * INC + c0));
                    const float4 v1 = __ldg((const float4*)(xs + s * INC + c0 + 4));
                    const float4 v2 = __ldg((const float4*)(xs + s * INC + c0 + 8));
                    xr[r][0]=v0.x; xr[r][1]=v0.y; xr[r][2]=v0.z; xr[r][3]=v0.w;
                    xr[r][4]=v1.x; xr[r][5]=v1.y; xr[r][6]=v1.z; xr[r][7]=v1.w;
                    xr[r][8]=v2.x; xr[r][9]=v2.y; xr[r][10]=v2.z; xr[r][11]=v2.w;
                } else {
#pragma unroll
                    for (int cc = 0; cc < 12; cc++) xr[r][cc] = 0.0f;
                }
            }
            for (int k = 0; k < NK; k++) {
                float acc[5];
                if (ch == 0) {
                    const float bk = __ldg(&conv_b[k]);
#pragma unroll
                    for (int i = 0; i < 5; i++) acc[i] = bk;
                } else {
#pragma unroll
                    for (int i = 0; i < 5; i++)
                        acc[i] = sCf[sp * SCST + k * SEQ + sq * 5 + i];
                }
#pragma unroll
                for (int cc = 0; cc < 12; cc++) {
                    const float w0 = scw[k * 72 + (c0 + cc) * 3 + 0];
                    const float w1 = scw[k * 72 + (c0 + cc) * 3 + 1];
                    const float w2 = scw[k * 72 + (c0 + cc) * 3 + 2];
#pragma unroll
                    for (int i = 0; i < 5; i++) {
                        acc[i] = fmaf(w0, xr[i][cc],     acc[i]);
                        acc[i] = fmaf(w1, xr[i + 1][cc], acc[i]);
                        acc[i] = fmaf(w2, xr[i + 2][cc], acc[i]);
                    }
                }
                if (ch == 0) {
#pragma unroll
                    for (int i = 0; i < 5; i++)
                        sCf[sp * SCST + k * SEQ + sq * 5 + i] = acc[i];
                } else {
#pragma unroll
                    for (int i = 0; i < 5; i++) {
                        const float v  = acc[i];
                        const float sg = fmaf(0.5f, tanhap(0.5f * v), 0.5f);
                        sC[sp * SCST + k * SEQ + sq * 5 + i] = f2tf(v * sg);
                    }
                }
            }
        }
    }
    __syncthreads();

    // ---- enc1 via tf32 mma, double-buffered weight chunks ----
    const int w    = tid >> 5;
    const int lane = tid & 31;
    const int g    = lane >> 2;
    const int tig  = lane & 3;
    const int mh   = w & 1;
    const int nq   = w >> 1;
    const int srow = mh * 16 + g;
    const int nbase = nq * 32;

    float c[4][4];
#pragma unroll
    for (int nt = 0; nt < 4; nt++) {
        const int n0 = nbase + nt * 8 + 2 * tig;
        c[nt][0] = __ldg(&enc1_b[n0]);
        c[nt][1] = __ldg(&enc1_b[n0 + 1]);
        c[nt][2] = c[nt][0];
        c[nt][3] = c[nt][1];
    }

    float4 pre[4];
    {
#pragma unroll
        for (int j = 0; j < 4; j++) {
            const int f  = tid + j * 256;
            const int oc = f >> 3, qd = f & 7;
            pre[j] = __ldg((const float4*)(enc1_w + (size_t)oc * FLAT + qd * 4));
        }
    }

    for (int kci = 0; kci < NCHUNK; kci++) {
        unsigned* buf = (kci & 1) ? sW1 : sW0;
#pragma unroll
        for (int j = 0; j < 4; j++) {
            const int f  = tid + j * 256;
            const int oc = f >> 3, qd = f & 7;
            uint4 u;
            u.x = f2tf(pre[j].x); u.y = f2tf(pre[j].y);
            u.z = f2tf(pre[j].z); u.w = f2tf(pre[j].w);
            *(uint4*)(buf + oc * SWST + qd * 4) = u;
        }
        if (kci + 1 < NCHUNK) {
            const int kc = (kci + 1) * 32;
#pragma unroll
            for (int j = 0; j < 4; j++) {
                const int f  = tid + j * 256;
                const int oc = f >> 3, qd = f & 7;
                pre[j] = __ldg((const float4*)(enc1_w + (size_t)oc * FLAT + kc + qd * 4));
            }
        }
        __syncthreads();
        const int kc = kci * 32;
#pragma unroll
        for (int kt = 0; kt < 4; kt++) {
            unsigned a[4];
            const unsigned* ar = sC + srow * SCST + kc + kt * 8 + tig;
            a[0] = ar[0];
            a[1] = ar[8 * SCST];
            a[2] = ar[4];
            a[3] = ar[8 * SCST + 4];
#pragma unroll
            for (int nt = 0; nt < 4; nt++) {
                const unsigned* br = buf + (nbase + nt * 8 + g) * SWST + kt * 8 + tig;
                mma_tf32(c[nt], a, br[0], br[4]);
            }
        }
    }
    __syncthreads();

#pragma unroll
    for (int nt = 0; nt < 4; nt++) {
        const int n0 = nbase + nt * 8 + 2 * tig;
        sH1[srow * SH1ST + n0]           = fmaxf(c[nt][0], 0.0f);
        sH1[srow * SH1ST + n0 + 1]       = fmaxf(c[nt][1], 0.0f);
        sH1[(srow + 8) * SH1ST + n0]     = fmaxf(c[nt][2], 0.0f);
        sH1[(srow + 8) * SH1ST + n0 + 1] = fmaxf(c[nt][3], 0.0f);
    }
    __syncthreads();

    for (int t = tid; t < ENC_SPB * HID; t += 256) {
        const int oc = t >> 5;
        const int sp = t & 31;
        float acc = __ldg(&enc2_b[oc]);
        const float* wr = enc2_w + oc * 128;
        const float* hv = sH1 + sp * SH1ST;
#pragma unroll
        for (int i = 0; i < 128; i += 4) {
            const float4 wv = __ldg((const float4*)(wr + i));
            const float4 h4 = *(const float4*)(hv + i);
            acc = fmaf(wv.x, h4.x, fmaf(wv.y, h4.y, fmaf(wv.z, h4.z, fmaf(wv.w, h4.w, acc))));
        }
        g_theta0[(size_t)oc * B + blk * ENC_SPB + sp] = acc;
    }
}

// ================================ ODE ======================================
// 32 samples/CTA, 256 threads = 8 warps; fp16 m16n8k16, W in A-frags (regs).
// Activation layout: fp16 [sample n][dim k], row stride KW=36 words (72 halves).
#define ODE_SPB 32
#define KW 36

// c[nt] = bias + W * in   (in: fp16 pairs in SMEM)
__device__ __forceinline__ void gemm16h(
    const unsigned (&A)[4][4], const unsigned* __restrict__ sIn,
    float blo, float bhi, int nbase, int g, int tig, float (&c)[2][4])
{
#pragma unroll
    for (int nt = 0; nt < 2; nt++) {
        c[nt][0] = blo; c[nt][1] = blo; c[nt][2] = bhi; c[nt][3] = bhi;
    }
#pragma unroll
    for (int kt = 0; kt < 4; kt++) {
#pragma unroll
        for (int nt = 0; nt < 2; nt++) {
            const unsigned* r = sIn + (nbase + nt * 8 + g) * KW + kt * 8 + tig;
            mma_fp16(c[nt], A[kt], r[0], r[4]);
        }
    }
}

// store C-frag (fp32) as fp16 into [n][k=m] layout
__device__ __forceinline__ void store_frag_h(
    unsigned* __restrict__ dst, const float (&c)[2][4],
    int m0, int nbase, int tig)
{
    __half* d = (__half*)dst;
#pragma unroll
    for (int nt = 0; nt < 2; nt++) {
        const int n0 = nbase + nt * 8 + 2 * tig;
        d[(n0)     * (2*KW) + m0]     = __float2half_rn(c[nt][0]);
        d[(n0 + 1) * (2*KW) + m0]     = __float2half_rn(c[nt][1]);
        d[(n0)     * (2*KW) + m0 + 8] = __float2half_rn(c[nt][2]);
        d[(n0 + 1) * (2*KW) + m0 + 8] = __float2half_rn(c[nt][3]);
    }
}

// full f: sY -> k frags.  ONE internal barrier; caller barriers before reuse.
__device__ __forceinline__ void eval_fh(
    const unsigned (&A1)[4][4], const unsigned (&A2)[4][4],
    float b1lo, float b1hi, float b2lo, float b2hi,
    const unsigned* __restrict__ sY, unsigned* __restrict__ sH,
    int m0, int nbase, int g, int tig, float (&k)[2][4])
{
    float h[2][4];
    gemm16h(A1, sY, b1lo, b1hi, nbase, g, tig, h);
#pragma unroll
    for (int nt = 0; nt < 2; nt++)
#pragma unroll
        for (int e = 0; e < 4; e++) h[nt][e] = tanhap(h[nt][e]);
    store_frag_h(sH, h, m0, nbase, tig);
    __syncthreads();     // all gemm1 sY reads done; sH complete
    gemm16h(A2, sH, b2lo, b2hi, nbase, g, tig, k);
}

__global__ void __launch_bounds__(256, 2) ode_kernel(
    const float* __restrict__ t_span,
    const float* __restrict__ w1g, const float* __restrict__ b1g,
    const float* __restrict__ w2g, const float* __restrict__ b2g,
    const float* __restrict__ r1w, const float* __restrict__ r1b,
    const float* __restrict__ r2w, const float* __restrict__ r2b,
    float* __restrict__ out, int B)
{
    __shared__ unsigned sODE[2 * ODE_SPB * KW];    // sY | sH (fp16 pairs)
    unsigned* sY = sODE;
    unsigned* sH = sODE + ODE_SPB * KW;

    const int tid  = threadIdx.x;
    const int w    = tid >> 5;
    const int lane = tid & 31;
    const int g    = lane >> 2;
    const int tig  = lane & 3;
    const int mw   = w & 3;
    const int nh   = w >> 2;
    const int m0   = mw * 16 + g;
    const int nbase = nh * 16;

    // ---- W1/W2 as fp16 A-fragments (m16n8k16) ----
    unsigned A1[4][4], A2[4][4];
#pragma unroll
    for (int kt = 0; kt < 4; kt++) {
        const int k0 = kt * 16 + 2 * tig;
        A1[kt][0] = pkh2(__ldg(&w1g[(m0)     * HID + k0]),     __ldg(&w1g[(m0)     * HID + k0 + 1]));
        A1[kt][1] = pkh2(__ldg(&w1g[(m0 + 8) * HID + k0]),     __ldg(&w1g[(m0 + 8) * HID + k0 + 1]));
        A1[kt][2] = pkh2(__ldg(&w1g[(m0)     * HID + k0 + 8]), __ldg(&w1g[(m0)     * HID + k0 + 9]));
        A1[kt][3] = pkh2(__ldg(&w1g[(m0 + 8) * HID + k0 + 8]), __ldg(&w1g[(m0 + 8) * HID + k0 + 9]));
        A2[kt][0] = pkh2(__ldg(&w2g[(m0)     * HID + k0]),     __ldg(&w2g[(m0)     * HID + k0 + 1]));
        A2[kt][1] = pkh2(__ldg(&w2g[(m0 + 8) * HID + k0]),     __ldg(&w2g[(m0 + 8) * HID + k0 + 1]));
        A2[kt][2] = pkh2(__ldg(&w2g[(m0)     * HID + k0 + 8]), __ldg(&w2g[(m0)     * HID + k0 + 9]));
        A2[kt][3] = pkh2(__ldg(&w2g[(m0 + 8) * HID + k0 + 8]), __ldg(&w2g[(m0 + 8) * HID + k0 + 9]));
    }
    const float b1lo = __ldg(&b1g[m0]), b1hi = __ldg(&b1g[m0 + 8]);
    const float b2lo = __ldg(&b2g[m0]), b2hi = __ldg(&b2g[m0 + 8]);

    const float dt = (__ldg(&t_span[1]) - __ldg(&t_span[0])) * (1.0f / STEPS);

    const long long gbase = (long long)blockIdx.x * ODE_SPB;
    float y[2][4];
#pragma unroll
    for (int nt = 0; nt < 2; nt++) {
        const long long n0 = gbase + nbase + nt * 8 + 2 * tig;
        y[nt][0] = __ldg(&g_theta0[(size_t)m0 * B + n0]);
        y[nt][1] = __ldg(&g_theta0[(size_t)m0 * B + n0 + 1]);
        y[nt][2] = __ldg(&g_theta0[(size_t)(m0 + 8) * B + n0]);
        y[nt][3] = __ldg(&g_theta0[(size_t)(m0 + 8) * B + n0 + 1]);
    }
    store_frag_h(sY, y, m0, nbase, tig);
    __syncthreads();

    float k1[2][4], k2[2][4], k3[2][4], k4[2][4], k5[2][4], k6[2][4], nv[2][4];

#define ELEM_LOOP(expr)                                                        \
    _Pragma("unroll") for (int nt = 0; nt < 2; nt++)                           \
    _Pragma("unroll") for (int e = 0; e < 4; e++) { expr; }

    for (int step = 0; step < STEPS; step++) {
        eval_fh(A1, A2, b1lo, b1hi, b2lo, b2hi, sY, sH, m0, nbase, g, tig, k1);
        {
            const float c1 = dt * 0.2f;
            ELEM_LOOP(nv[nt][e] = fmaf(c1, k1[nt][e], y[nt][e]));
            store_frag_h(sY, nv, m0, nbase, tig);
        }
        __syncthreads();
        eval_fh(A1, A2, b1lo, b1hi, b2lo, b2hi, sY, sH, m0, nbase, g, tig, k2);
        {
            const float c1 = dt * (3.0f / 40.0f), c2 = dt * (9.0f / 40.0f);
            ELEM_LOOP(nv[nt][e] = fmaf(c1, k1[nt][e], fmaf(c2, k2[nt][e], y[nt][e])));
            store_frag_h(sY, nv, m0, nbase, tig);
        }
        __syncthreads();
        eval_fh(A1, A2, b1lo, b1hi, b2lo, b2hi, sY, sH, m0, nbase, g, tig, k3);
        {
            const float c1 = dt * (44.0f / 45.0f), c2 = dt * (-56.0f / 15.0f),
                        c3 = dt * (32.0f / 9.0f);
            ELEM_LOOP(nv[nt][e] = fmaf(c1, k1[nt][e], fmaf(c2, k2[nt][e],
                                  fmaf(c3, k3[nt][e], y[nt][e]))));
            store_frag_h(sY, nv, m0, nbase, tig);
        }
        __syncthreads();
        eval_fh(A1, A2, b1lo, b1hi, b2lo, b2hi, sY, sH, m0, nbase, g, tig, k4);
        {
            const float c1 = dt * (19372.0f / 6561.0f), c2 = dt * (-25360.0f / 2187.0f),
                        c3 = dt * (64448.0f / 6561.0f), c4 = dt * (-212.0f / 729.0f);
            ELEM_LOOP(nv[nt][e] = fmaf(c1, k1[nt][e], fmaf(c2, k2[nt][e],
                                  fmaf(c3, k3[nt][e], fmaf(c4, k4[nt][e], y[nt][e])))));
            store_frag_h(sY, nv, m0, nbase, tig);
        }
        __syncthreads();
        eval_fh(A1, A2, b1lo, b1hi, b2lo, b2hi, sY, sH, m0, nbase, g, tig, k5);
        {
            const float c1 = dt * (9017.0f / 3168.0f), c2 = dt * (-355.0f / 33.0f),
                        c3 = dt * (46732.0f / 5247.0f), c4 = dt * (49.0f / 176.0f),
                        c5 = dt * (-5103.0f / 18656.0f);
            ELEM_LOOP(nv[nt][e] = fmaf(c1, k1[nt][e], fmaf(c2, k2[nt][e],
                                  fmaf(c3, k3[nt][e], fmaf(c4, k4[nt][e],
                                  fmaf(c5, k5[nt][e], y[nt][e]))))));
            store_frag_h(sY, nv, m0, nbase, tig);
        }
        __syncthreads();
        eval_fh(A1, A2, b1lo, b1hi, b2lo, b2hi, sY, sH, m0, nbase, g, tig, k6);
        {
            const float c1 = dt * (35.0f / 384.0f),  c3 = dt * (500.0f / 1113.0f),
                        c4 = dt * (125.0f / 192.0f), c5 = dt * (-2187.0f / 6784.0f),
                        c6 = dt * (11.0f / 84.0f);
            ELEM_LOOP(y[nt][e] = fmaf(c1, k1[nt][e], fmaf(c3, k3[nt][e],
                                 fmaf(c4, k4[nt][e], fmaf(c5, k5[nt][e],
                                 fmaf(c6, k6[nt][e], y[nt][e]))))));
            store_frag_h(sY, y, m0, nbase, tig);
        }
        __syncthreads();
    }

    // ---- write final y (fp32) into [sample][dim] layout over sODE ----
    {
        float* sYf = (float*)sODE;                 // [32][68] floats (8704B<=9216B)
#pragma unroll
        for (int nt = 0; nt < 2; nt++) {
            const int n0 = nbase + nt * 8 + 2 * tig;
            sYf[(n0)     * 68 + m0]     = y[nt][0];
            sYf[(n0 + 1) * 68 + m0]     = y[nt][1];
            sYf[(n0)     * 68 + m0 + 8] = y[nt][2];
            sYf[(n0 + 1) * 68 + m0 + 8] = y[nt][3];
        }
    }
    __syncthreads();

    // ---- regressor: threads 0..127, 4 per sample ----
    if (tid < 128) {
        const float* sYf = (const float*)sODE;
        const int s  = tid >> 2;
        const int mg = (tid & 3) * 8;
        float accm[8];
#pragma unroll
        for (int m = 0; m < 8; m++) accm[m] = __ldg(&r1b[mg + m]);
        for (int i = 0; i < HID; i++) {
            const float yy = sYf[s * 68 + i];
#pragma unroll
            for (int m = 0; m < 8; m++)
                accm[m] = fmaf(__ldg(&r1w[(mg + m) * HID + i]), yy, accm[m]);
        }
        float part = 0.0f;
#pragma unroll
        for (int m = 0; m < 8; m++)
            part = fmaf(__ldg(&r2w[mg + m]), fmaxf(accm[m], 0.0f), part);
        part += __shfl_xor_sync(0xffffffffu, part, 1);
        part += __shfl_xor_sync(0xffffffffu, part, 2);
        if ((tid & 3) == 0)
            out[(long long)blockIdx.x * ODE_SPB + s] = part + __ldg(&r2b[0]);
    }
}

// ============================== launch ======================================
extern "C" void kernel_launch(void* const* d_in, const int* in_sizes, int n_in,
                              void* d_out, int out_size)
{
    const float* x      = (const float*)d_in[0];
    const float* t_span = (const float*)d_in[1];
    const float* conv_w = (const float*)d_in[2];
    const float* conv_b = (const float*)d_in[3];
    const float* enc1_w = (const float*)d_in[4];
    const float* enc1_b = (const float*)d_in[5];
    const float* enc2_w = (const float*)d_in[6];
    const float* enc2_b = (const float*)d_in[7];
    const float* ode1_w = (const float*)d_in[8];
    const float* ode1_b = (const float*)d_in[9];
    const float* ode2_w = (const float*)d_in[10];
    const float* ode2_b = (const float*)d_in[11];
    const float* reg1_w = (const float*)d_in[12];
    const float* reg1_b = (const float*)d_in[13];
    const float* reg2_w = (const float*)d_in[14];
    const float* reg2_b = (const float*)d_in[15];
    float* out = (float*)d_out;

    const int B = in_sizes[0] / (SEQ * INC);

    cudaFuncSetAttribute(enc_kernel, cudaFuncAttributeMaxDynamicSharedMemorySize,
                         ENC_SMEM_BYTES);

    enc_kernel<<<B / ENC_SPB, 256, ENC_SMEM_BYTES>>>(
        x, conv_w, conv_b, enc1_w, enc1_b, enc2_w, enc2_b, B);
    ode_kernel<<<B / ODE_SPB, 256>>>(
        t_span, ode1_w, ode1_b, ode2_w, ode2_b,
        reg1_w, reg1_b, reg2_w, reg2_b, out, B);
}

// round 12
// speedup vs baseline: 9.7576x; 1.0002x over previous
#include <cuda_runtime.h>
#include <cuda_bf16.h>
#include <cuda_fp16.h>

// ---------------------------------------------------------------------------
// CNN_ODE: conv1d+SiLU -> MLP encoder (tf32 mma, double-buffered) -> 50-step
// fixed dopri5 (64-dim neural ODE, fp16 m16n8k16 mma) -> regressor.  B=65536.
// ---------------------------------------------------------------------------

#define SEQ   40
#define INC   24
#define NK    36
#define FLAT  1440
#define HID   64
#define STEPS 50

// theta0 scratch, TRANSPOSED: [dim][sample], float
__device__ float g_theta0[HID * 65536];   // 16 MB

__device__ __forceinline__ float tanhap(float x) {
    float r; asm("tanh.approx.f32 %0,%1;" : "=f"(r) : "f"(x)); return r;
}
__device__ __forceinline__ unsigned f2tf(float f) {
    unsigned u; asm("cvt.rna.tf32.f32 %0,%1;" : "=r"(u) : "f"(f)); return u;
}
__device__ __forceinline__ void mma_tf32(
    float (&c)[4], const unsigned (&a)[4], unsigned b0, unsigned b1)
{
    asm("mma.sync.aligned.m16n8k8.row.col.f32.tf32.tf32.f32 "
        "{%0,%1,%2,%3},{%4,%5,%6,%7},{%8,%9},{%0,%1,%2,%3};"
        : "+f"(c[0]), "+f"(c[1]), "+f"(c[2]), "+f"(c[3])
        : "r"(a[0]), "r"(a[1]), "r"(a[2]), "r"(a[3]), "r"(b0), "r"(b1));
}
__device__ __forceinline__ void mma_fp16(
    float (&c)[4], const unsigned (&a)[4], unsigned b0, unsigned b1)
{
    asm("mma.sync.aligned.m16n8k16.row.col.f32.f16.f16.f32 "
        "{%0,%1,%2,%3},{%4,%5,%6,%7},{%8,%9},{%0,%1,%2,%3};"
        : "+f"(c[0]), "+f"(c[1]), "+f"(c[2]), "+f"(c[3])
        : "r"(a[0]), "r"(a[1]), "r"(a[2]), "r"(a[3]), "r"(b0), "r"(b1));
}
__device__ __forceinline__ unsigned pkh2(float a, float b) {
    __half2 h = __floats2half2_rn(a, b);
    return *reinterpret_cast<unsigned*>(&h);
}

// ============================== Encoder ====================================
// 32 samples/CTA, 256 threads.  (unchanged from R10)
#define ENC_SPB 32
#define SCST    1444
#define SWST    36
#define SH1ST   132
#define NCHUNK  (FLAT / 32)            // 45
#define ENC_SMEM_BYTES ((ENC_SPB*SCST + 2*128*SWST) * 4)

__global__ void __launch_bounds__(256) enc_kernel(
    const float* __restrict__ x,
    const float* __restrict__ conv_w, const float* __restrict__ conv_b,
    const float* __restrict__ enc1_w, const float* __restrict__ enc1_b,
    const float* __restrict__ enc2_w, const float* __restrict__ enc2_b,
    int B)
{
    extern __shared__ unsigned smu[];
    unsigned* sC  = smu;                          // [32][SCST] tf32 after conv
    unsigned* sW0 = sC + ENC_SPB * SCST;          // [128][SWST]
    unsigned* sW1 = sW0 + 128 * SWST;             // [128][SWST]
    float*    sH1 = (float*)sC;                   // [32][SH1ST] (aliases sC)

    const int tid = threadIdx.x;
    const long long blk = blockIdx.x;

    float* scw = (float*)sW0;
    for (int i = tid; i < NK * 72; i += 256) scw[i] = conv_w[i];
    __syncthreads();

    // ---- conv1d (pad=1) + fused SiLU/tf32 on second c-half ----
    {
        const int sp = tid >> 3;
        const int sq = tid & 7;
        const float* xs = x + (blk * ENC_SPB + sp) * (SEQ * INC);
        float* sCf = (float*)sC;
#pragma unroll
        for (int ch = 0; ch < 2; ch++) {
            const int c0 = ch * 12;
            float xr[7][12];
#pragma unroll
            for (int r = 0; r < 7; r++) {
                const int s = sq * 5 - 1 + r;
                if (s >= 0 && s < SEQ) {
                    const float4 v0 = __ldg((const float4*)(xs + s * INC + c0));
                    const float4 v1 = __ldg((const float4*)(xs + s * INC + c0 + 4));
                    const float4 v2 = __ldg((const float4*)(xs + s * INC + c0 + 8));
                    xr[r][0]=v0.x; xr[r][1]=v0.y; xr[r][2]=v0.z; xr[r][3]=v0.w;
                    xr[r][4]=v1.x; xr[r][5]=v1.y; xr[r][6]=v1.z; xr[r][7]=v1.w;
                    xr[r][8]=v2.x; xr[r][9]=v2.y; xr[r][10]=v2.z; xr[r][11]=v2.w;
                } else {
#pragma unroll
                    for (int cc = 0; cc < 12; cc++) xr[r][cc] = 0.0f;
                }
            }
            for (int k = 0; k < NK; k++) {
                float acc[5];
                if (ch == 0) {
                    const float bk = __ldg(&conv_b[k]);
#pragma unroll
                    for (int i = 0; i < 5; i++) acc[i] = bk;
                } else {
#pragma unroll
                    for (int i = 0; i < 5; i++)
                        acc[i] = sCf[sp * SCST + k * SEQ + sq * 5 + i];
                }
#pragma unroll
                for (int cc = 0; cc < 12; cc++) {
                    const float w0 = scw[k * 72 + (c0 + cc) * 3 + 0];
                    const float w1 = scw[k * 72 + (c0 + cc) * 3 + 1];
                    const float w2 = scw[k * 72 + (c0 + cc) * 3 + 2];
#pragma unroll
                    for (int i = 0; i < 5; i++) {
                        acc[i] = fmaf(w0, xr[i][cc],     acc[i]);
                        acc[i] = fmaf(w1, xr[i + 1][cc], acc[i]);
                        acc[i] = fmaf(w2, xr[i + 2][cc], acc[i]);
                    }
                }
                if (ch == 0) {
#pragma unroll
                    for (int i = 0; i < 5; i++)
                        sCf[sp * SCST + k * SEQ + sq * 5 + i] = acc[i];
                } else {
#pragma unroll
                    for (int i = 0; i < 5; i++) {
                        const float v  = acc[i];
                        const float sg = fmaf(0.5f, tanhap(0.5f * v), 0.5f);
                        sC[sp * SCST + k * SEQ + sq * 5 + i] = f2tf(v * sg);
                    }
                }
            }
        }
    }
    __syncthreads();

    // ---- enc1 via tf32 mma, double-buffered weight chunks ----
    const int w    = tid >> 5;
    const int lane = tid & 31;
    const int g    = lane >> 2;
    const int tig  = lane & 3;
    const int mh   = w & 1;
    const int nq   = w >> 1;
    const int srow = mh * 16 + g;
    const int nbase = nq * 32;

    float c[4][4];
#pragma unroll
    for (int nt = 0; nt < 4; nt++) {
        const int n0 = nbase + nt * 8 + 2 * tig;
        c[nt][0] = __ldg(&enc1_b[n0]);
        c[nt][1] = __ldg(&enc1_b[n0 + 1]);
        c[nt][2] = c[nt][0];
        c[nt][3] = c[nt][1];
    }

    float4 pre[4];
    {
#pragma unroll
        for (int j = 0; j < 4; j++) {
            const int f  = tid + j * 256;
            const int oc = f >> 3, qd = f & 7;
            pre[j] = __ldg((const float4*)(enc1_w + (size_t)oc * FLAT + qd * 4));
        }
    }

    for (int kci = 0; kci < NCHUNK; kci++) {
        unsigned* buf = (kci & 1) ? sW1 : sW0;
#pragma unroll
        for (int j = 0; j < 4; j++) {
            const int f  = tid + j * 256;
            const int oc = f >> 3, qd = f & 7;
            uint4 u;
            u.x = f2tf(pre[j].x); u.y = f2tf(pre[j].y);
            u.z = f2tf(pre[j].z); u.w = f2tf(pre[j].w);
            *(uint4*)(buf + oc * SWST + qd * 4) = u;
        }
        if (kci + 1 < NCHUNK) {
            const int kc = (kci + 1) * 32;
#pragma unroll
            for (int j = 0; j < 4; j++) {
                const int f  = tid + j * 256;
                const int oc = f >> 3, qd = f & 7;
                pre[j] = __ldg((const float4*)(enc1_w + (size_t)oc * FLAT + kc + qd * 4));
            }
        }
        __syncthreads();
        const int kc = kci * 32;
#pragma unroll
        for (int kt = 0; kt < 4; kt++) {
            unsigned a[4];
            const unsigned* ar = sC + srow * SCST + kc + kt * 8 + tig;
            a[0] = ar[0];
            a[1] = ar[8 * SCST];
            a[2] = ar[4];
            a[3] = ar[8 * SCST + 4];
#pragma unroll
            for (int nt = 0; nt < 4; nt++) {
                const unsigned* br = buf + (nbase + nt * 8 + g) * SWST + kt * 8 + tig;
                mma_tf32(c[nt], a, br[0], br[4]);
            }
        }
    }
    __syncthreads();

#pragma unroll
    for (int nt = 0; nt < 4; nt++) {
        const int n0 = nbase + nt * 8 + 2 * tig;
        sH1[srow * SH1ST + n0]           = fmaxf(c[nt][0], 0.0f);
        sH1[srow * SH1ST + n0 + 1]       = fmaxf(c[nt][1], 0.0f);
        sH1[(srow + 8) * SH1ST + n0]     = fmaxf(c[nt][2], 0.0f);
        sH1[(srow + 8) * SH1ST + n0 + 1] = fmaxf(c[nt][3], 0.0f);
    }
    __syncthreads();

    for (int t = tid; t < ENC_SPB * HID; t += 256) {
        const int oc = t >> 5;
        const int sp = t & 31;
        float acc = __ldg(&enc2_b[oc]);
        const float* wr = enc2_w + oc * 128;
        const float* hv = sH1 + sp * SH1ST;
#pragma unroll
        for (int i = 0; i < 128; i += 4) {
            const float4 wv = __ldg((const float4*)(wr + i));
            const float4 h4 = *(const float4*)(hv + i);
            acc = fmaf(wv.x, h4.x, fmaf(wv.y, h4.y, fmaf(wv.z, h4.z, fmaf(wv.w, h4.w, acc))));
        }
        g_theta0[(size_t)oc * B + blk * ENC_SPB + sp] = acc;
    }
}

// ================================ ODE ======================================
// 32 samples/CTA, 256 threads = 8 warps; fp16 m16n8k16, W in A-frags (regs).
// Activation layout: fp16 [sample n][dim k], row stride KW=36 words (72 halves).
#define ODE_SPB 32
#define KW 36

// c[nt] = bias + W * in   (in: fp16 pairs in SMEM)
__device__ __forceinline__ void gemm16h(
    const unsigned (&A)[4][4], const unsigned* __restrict__ sIn,
    float blo, float bhi, int nbase, int g, int tig, float (&c)[2][4])
{
#pragma unroll
    for (int nt = 0; nt < 2; nt++) {
        c[nt][0] = blo; c[nt][1] = blo; c[nt][2] = bhi; c[nt][3] = bhi;
    }
#pragma unroll
    for (int kt = 0; kt < 4; kt++) {
#pragma unroll
        for (int nt = 0; nt < 2; nt++) {
            const unsigned* r = sIn + (nbase + nt * 8 + g) * KW + kt * 8 + tig;
            mma_fp16(c[nt], A[kt], r[0], r[4]);
        }
    }
}

// store C-frag (fp32) as fp16 into [n][k=m] layout
__device__ __forceinline__ void store_frag_h(
    unsigned* __restrict__ dst, const float (&c)[2][4],
    int m0, int nbase, int tig)
{
    __half* d = (__half*)dst;
#pragma unroll
    for (int nt = 0; nt < 2; nt++) {
        const int n0 = nbase + nt * 8 + 2 * tig;
        d[(n0)     * (2*KW) + m0]     = __float2half_rn(c[nt][0]);
        d[(n0 + 1) * (2*KW) + m0]     = __float2half_rn(c[nt][1]);
        d[(n0)     * (2*KW) + m0 + 8] = __float2half_rn(c[nt][2]);
        d[(n0 + 1) * (2*KW) + m0 + 8] = __float2half_rn(c[nt][3]);
    }
}

// full f: sY -> k frags.  ONE internal barrier; caller barriers before reuse.
__device__ __forceinline__ void eval_fh(
    const unsigned (&A1)[4][4], const unsigned (&A2)[4][4],
    float b1lo, float b1hi, float b2lo, float b2hi,
    const unsigned* __restrict__ sY, unsigned* __restrict__ sH,
    int m0, int nbase, int g, int tig, float (&k)[2][4])
{
    float h[2][4];
    gemm16h(A1, sY, b1lo, b1hi, nbase, g, tig, h);
#pragma unroll
    for (int nt = 0; nt < 2; nt++)
#pragma unroll
        for (int e = 0; e < 4; e++) h[nt][e] = tanhap(h[nt][e]);
    store_frag_h(sH, h, m0, nbase, tig);
    __syncthreads();     // all gemm1 sY reads done; sH complete
    gemm16h(A2, sH, b2lo, b2hi, nbase, g, tig, k);
}

__global__ void __launch_bounds__(256, 2) ode_kernel(
    const float* __restrict__ t_span,
    const float* __restrict__ w1g, const float* __restrict__ b1g,
    const float* __restrict__ w2g, const float* __restrict__ b2g,
    const float* __restrict__ r1w, const float* __restrict__ r1b,
    const float* __restrict__ r2w, const float* __restrict__ r2b,
    float* __restrict__ out, int B)
{
    __shared__ unsigned sODE[2 * ODE_SPB * KW];    // sY | sH (fp16 pairs)
    unsigned* sY = sODE;
    unsigned* sH = sODE + ODE_SPB * KW;

    const int tid  = threadIdx.x;
    const int w    = tid >> 5;
    const int lane = tid & 31;
    const int g    = lane >> 2;
    const int tig  = lane & 3;
    const int mw   = w & 3;
    const int nh   = w >> 2;
    const int m0   = mw * 16 + g;
    const int nbase = nh * 16;

    // ---- W1/W2 as fp16 A-fragments (m16n8k16) ----
    unsigned A1[4][4], A2[4][4];
#pragma unroll
    for (int kt = 0; kt < 4; kt++) {
        const int k0 = kt * 16 + 2 * tig;
        A1[kt][0] = pkh2(__ldg(&w1g[(m0)     * HID + k0]),     __ldg(&w1g[(m0)     * HID + k0 + 1]));
        A1[kt][1] = pkh2(__ldg(&w1g[(m0 + 8) * HID + k0]),     __ldg(&w1g[(m0 + 8) * HID + k0 + 1]));
        A1[kt][2] = pkh2(__ldg(&w1g[(m0)     * HID + k0 + 8]), __ldg(&w1g[(m0)     * HID + k0 + 9]));
        A1[kt][3] = pkh2(__ldg(&w1g[(m0 + 8) * HID + k0 + 8]), __ldg(&w1g[(m0 + 8) * HID + k0 + 9]));
        A2[kt][0] = pkh2(__ldg(&w2g[(m0)     * HID + k0]),     __ldg(&w2g[(m0)     * HID + k0 + 1]));
        A2[kt][1] = pkh2(__ldg(&w2g[(m0 + 8) * HID + k0]),     __ldg(&w2g[(m0 + 8) * HID + k0 + 1]));
        A2[kt][2] = pkh2(__ldg(&w2g[(m0)     * HID + k0 + 8]), __ldg(&w2g[(m0)     * HID + k0 + 9]));
        A2[kt][3] = pkh2(__ldg(&w2g[(m0 + 8) * HID + k0 + 8]), __ldg(&w2g[(m0 + 8) * HID + k0 + 9]));
    }
    const float b1lo = __ldg(&b1g[m0]), b1hi = __ldg(&b1g[m0 + 8]);
    const float b2lo = __ldg(&b2g[m0]), b2hi = __ldg(&b2g[m0 + 8]);

    const float dt = (__ldg(&t_span[1]) - __ldg(&t_span[0])) * (1.0f / STEPS);

    const long long gbase = (long long)blockIdx.x * ODE_SPB;
    float y[2][4];
#pragma unroll
    for (int nt = 0; nt < 2; nt++) {
        const long long n0 = gbase + nbase + nt * 8 + 2 * tig;
        y[nt][0] = __ldg(&g_theta0[(size_t)m0 * B + n0]);
        y[nt][1] = __ldg(&g_theta0[(size_t)m0 * B + n0 + 1]);
        y[nt][2] = __ldg(&g_theta0[(size_t)(m0 + 8) * B + n0]);
        y[nt][3] = __ldg(&g_theta0[(size_t)(m0 + 8) * B + n0 + 1]);
    }
    store_frag_h(sY, y, m0, nbase, tig);
    __syncthreads();

    float k1[2][4], k2[2][4], k3[2][4], k4[2][4], k5[2][4], k6[2][4], nv[2][4];

#define ELEM_LOOP(expr)                                                        \
    _Pragma("unroll") for (int nt = 0; nt < 2; nt++)                           \
    _Pragma("unroll") for (int e = 0; e < 4; e++) { expr; }

    for (int step = 0; step < STEPS; step++) {
        eval_fh(A1, A2, b1lo, b1hi, b2lo, b2hi, sY, sH, m0, nbase, g, tig, k1);
        {
            const float c1 = dt * 0.2f;
            ELEM_LOOP(nv[nt][e] = fmaf(c1, k1[nt][e], y[nt][e]));
            store_frag_h(sY, nv, m0, nbase, tig);
        }
        __syncthreads();
        eval_fh(A1, A2, b1lo, b1hi, b2lo, b2hi, sY, sH, m0, nbase, g, tig, k2);
        {
            const float c1 = dt * (3.0f / 40.0f), c2 = dt * (9.0f / 40.0f);
            ELEM_LOOP(nv[nt][e] = fmaf(c1, k1[nt][e], fmaf(c2, k2[nt][e], y[nt][e])));
            store_frag_h(sY, nv, m0, nbase, tig);
        }
        __syncthreads();
        eval_fh(A1, A2, b1lo, b1hi, b2lo, b2hi, sY, sH, m0, nbase, g, tig, k3);
        {
            const float c1 = dt * (44.0f / 45.0f), c2 = dt * (-56.0f / 15.0f),
                        c3 = dt * (32.0f / 9.0f);
            ELEM_LOOP(nv[nt][e] = fmaf(c1, k1[nt][e], fmaf(c2, k2[nt][e],
                                  fmaf(c3, k3[nt][e], y[nt][e]))));
            store_frag_h(sY, nv, m0, nbase, tig);
        }
        __syncthreads();
        eval_fh(A1, A2, b1lo, b1hi, b2lo, b2hi, sY, sH, m0, nbase, g, tig, k4);
        {
            const float c1 = dt * (19372.0f / 6561.0f), c2 = dt * (-25360.0f / 2187.0f),
                        c3 = dt * (64448.0f / 6561.0f), c4 = dt * (-212.0f / 729.0f);
            ELEM_LOOP(nv[nt][e] = fmaf(c1, k1[nt][e], fmaf(c2, k2[nt][e],
                                  fmaf(c3, k3[nt][e], fmaf(c4, k4[nt][e], y[nt][e])))));
            store_frag_h(sY, nv, m0, nbase, tig);
        }
        __syncthreads();
        eval_fh(A1, A2, b1lo, b1hi, b2lo, b2hi, sY, sH, m0, nbase, g, tig, k5);
        {
            const float c1 = dt * (9017.0f / 3168.0f), c2 = dt * (-355.0f / 33.0f),
                        c3 = dt * (46732.0f / 5247.0f), c4 = dt * (49.0f / 176.0f),
                        c5 = dt * (-5103.0f / 18656.0f);
            ELEM_LOOP(nv[nt][e] = fmaf(c1, k1[nt][e], fmaf(c2, k2[nt][e],
                                  fmaf(c3, k3[nt][e], fmaf(c4, k4[nt][e],
                                  fmaf(c5, k5[nt][e], y[nt][e]))))));
            store_frag_h(sY, nv, m0, nbase, tig);
        }
        __syncthreads();
        eval_fh(A1, A2, b1lo, b1hi, b2lo, b2hi, sY, sH, m0, nbase, g, tig, k6);
        {
            const float c1 = dt * (35.0f / 384.0f),  c3 = dt * (500.0f / 1113.0f),
                        c4 = dt * (125.0f / 192.0f), c5 = dt * (-2187.0f / 6784.0f),
                        c6 = dt * (11.0f / 84.0f);
            ELEM_LOOP(y[nt][e] = fmaf(c1, k1[nt][e], fmaf(c3, k3[nt][e],
                                 fmaf(c4, k4[nt][e], fmaf(c5, k5[nt][e],
                                 fmaf(c6, k6[nt][e], y[nt][e]))))));
            store_frag_h(sY, y, m0, nbase, tig);
        }
        __syncthreads();
    }

    // ---- write final y (fp32) into [sample][dim] layout over sODE ----
    {
        float* sYf = (float*)sODE;                 // [32][68] floats (8704B<=9216B)
#pragma unroll
        for (int nt = 0; nt < 2; nt++) {
            const int n0 = nbase + nt * 8 + 2 * tig;
            sYf[(n0)     * 68 + m0]     = y[nt][0];
            sYf[(n0 + 1) * 68 + m0]     = y[nt][1];
            sYf[(n0)     * 68 + m0 + 8] = y[nt][2];
            sYf[(n0 + 1) * 68 + m0 + 8] = y[nt][3];
        }
    }
    __syncthreads();

    // ---- regressor: threads 0..127, 4 per sample ----
    if (tid < 128) {
        const float* sYf = (const float*)sODE;
        const int s  = tid >> 2;
        const int mg = (tid & 3) * 8;
        float accm[8];
#pragma unroll
        for (int m = 0; m < 8; m++) accm[m] = __ldg(&r1b[mg + m]);
        for (int i = 0; i < HID; i++) {
            const float yy = sYf[s * 68 + i];
#pragma unroll
            for (int m = 0; m < 8; m++)
                accm[m] = fmaf(__ldg(&r1w[(mg + m) * HID + i]), yy, accm[m]);
        }
        float part = 0.0f;
#pragma unroll
        for (int m = 0; m < 8; m++)
            part = fmaf(__ldg(&r2w[mg + m]), fmaxf(accm[m], 0.0f), part);
        part += __shfl_xor_sync(0xffffffffu, part, 1);
        part += __shfl_xor_sync(0xffffffffu, part, 2);
        if ((tid & 3) == 0)
            out[(long long)blockIdx.x * ODE_SPB + s] = part + __ldg(&r2b[0]);
    }
}

// ============================== launch ======================================
extern "C" void kernel_launch(void* const* d_in, const int* in_sizes, int n_in,
                              void* d_out, int out_size)
{
    const float* x      = (const float*)d_in[0];
    const float* t_span = (const float*)d_in[1];
    const float* conv_w = (const float*)d_in[2];
    const float* conv_b = (const float*)d_in[3];
    const float* enc1_w = (const float*)d_in[4];
    const float* enc1_b = (const float*)d_in[5];
    const float* enc2_w = (const float*)d_in[6];
    const float* enc2_b = (const float*)d_in[7];
    const float* ode1_w = (const float*)d_in[8];
    const float* ode1_b = (const float*)d_in[9];
    const float* ode2_w = (const float*)d_in[10];
    const float* ode2_b = (const float*)d_in[11];
    const float* reg1_w = (const float*)d_in[12];
    const float* reg1_b = (const float*)d_in[13];
    const float* reg2_w = (const float*)d_in[14];
    const float* reg2_b = (const float*)d_in[15];
    float* out = (float*)d_out;

    const int B = in_sizes[0] / (SEQ * INC);

    cudaFuncSetAttribute(enc_kernel, cudaFuncAttributeMaxDynamicSharedMemorySize,
                         ENC_SMEM_BYTES);

    enc_kernel<<<B / ENC_SPB, 256, ENC_SMEM_BYTES>>>(
        x, conv_w, conv_b, enc1_w, enc1_b, enc2_w, enc2_b, B);
    ode_kernel<<<B / ODE_SPB, 256>>>(
        t_span, ode1_w, ode1_b, ode2_w, ode2_b,
        reg1_w, reg1_b, reg2_w, reg2_b, out, B);
}